// round 2
// baseline (speedup 1.0000x reference)
#include <cuda_runtime.h>
#include <cuda_bf16.h>
#include <math.h>

#define NEGMIN (-3.4028234663852886e38f)
#define EMB_SCALE 22.627416997969522f
#define LN_EPS 1e-5f

// ---------- device scratch (no allocations allowed) ----------
__device__ float g_buf [4*128*32];
__device__ float g_h   [4*128*512];
__device__ float g_qkv [4*128*1536];
__device__ float g_attn[4*128*512];
__device__ float g_t2  [2*512*512];
__device__ float g_ff  [512*2048];
__device__ float g_wqkv[4*1536*512];
__device__ float g_pe  [128*512];
__device__ float g_M   [2048*32];
__device__ float g_c1  [2048];

__device__ __forceinline__ float warp_sum(float v){
    v += __shfl_xor_sync(0xffffffffu, v, 16);
    v += __shfl_xor_sync(0xffffffffu, v, 8);
    v += __shfl_xor_sync(0xffffffffu, v, 4);
    v += __shfl_xor_sync(0xffffffffu, v, 2);
    v += __shfl_xor_sync(0xffffffffu, v, 1);
    return v;
}
__device__ __forceinline__ float warp_max(float v){
    v = fmaxf(v, __shfl_xor_sync(0xffffffffu, v, 16));
    v = fmaxf(v, __shfl_xor_sync(0xffffffffu, v, 8));
    v = fmaxf(v, __shfl_xor_sync(0xffffffffu, v, 4));
    v = fmaxf(v, __shfl_xor_sync(0xffffffffu, v, 2));
    v = fmaxf(v, __shfl_xor_sync(0xffffffffu, v, 1));
    return v;
}
__device__ __forceinline__ float gelu_f(float x){
    float x3 = x*x*x;
    return 0.5f*x*(1.0f + tanhf(0.7978845608028654f*(x + 0.044715f*x3)));
}

// ---------- prep kernels ----------
__global__ void init_buf_kernel(const float* __restrict__ hist){
    int idx = blockIdx.x*blockDim.x + threadIdx.x;
    if (idx >= 4*128*32) return;
    int i = idx & 31, t = (idx>>5)&127, b = idx>>12;
    g_buf[idx] = (t < 120) ? hist[(b*120 + t)*32 + i] : 0.0f;
}
__global__ void pack_qkv_kernel(const float* __restrict__ Wq, const float* __restrict__ Wk,
                                const float* __restrict__ Wv){
    int idx = blockIdx.x*blockDim.x + threadIdx.x;
    if (idx >= 4*1536*512) return;
    int l = idx/(1536*512);
    int r = idx - l*1536*512;
    int n = r>>9, k = r&511;
    float v;
    if (n < 512)       v = Wq[(l*512 + n      )*512 + k];
    else if (n < 1024) v = Wk[(l*512 + n - 512)*512 + k];
    else               v = Wv[(l*512 + n -1024)*512 + k];
    g_wqkv[idx] = v;
}
__global__ void prep_pe_kernel(){
    int idx = blockIdx.x*blockDim.x + threadIdx.x;
    if (idx >= 128*512) return;
    int d = idx & 511, t = idx>>9;
    double freq = exp((double)(d & ~1) * (-9.210340371976184/512.0));
    double ang = (double)t * freq;
    g_pe[idx] = (float)((d & 1) ? cos(ang) : sin(ang));
}
__global__ void prep_M_kernel(const float* __restrict__ Wr1, const float* __restrict__ W_emb,
                              const float* __restrict__ b_emb, const float* __restrict__ br1){
    int j = blockIdx.x, lane = threadIdx.x;
    const float* wr = Wr1 + j*1024;
    float a = 0.f;
    for (int k = 0; k < 512; k++) a = fmaf(wr[k], W_emb[k*32 + lane], a);
    g_M[j*32 + lane] = a * EMB_SCALE;
    float c = 0.f;
    for (int k = lane; k < 512; k += 32) c = fmaf(wr[k], b_emb[k], c);
    c = warp_sum(c);
    if (lane == 0) g_c1[j] = c * EMB_SCALE + br1[j];
}

// ---------- embedding: h = (buf @ W_emb^T + b_emb)*scale + pe ----------
__global__ __launch_bounds__(512) void embed_kernel(const float* __restrict__ W_emb,
                                                    const float* __restrict__ b_emb){
    __shared__ float xs[32];
    int bt = blockIdx.x, t = bt & 127;
    if (threadIdx.x < 32) xs[threadIdx.x] = g_buf[bt*32 + threadIdx.x];
    __syncthreads();
    int d = threadIdx.x;
    const float* wr = W_emb + d*32;
    float acc = 0.f;
#pragma unroll
    for (int i = 0; i < 32; i++) acc = fmaf(wr[i], xs[i], acc);
    g_h[bt*512 + d] = (acc + b_emb[d]) * EMB_SCALE + g_pe[t*512 + d];
}

// ---------- GEMM: C[M,N] = A[M,K] @ W[N,K]^T, 64x64 tile, optional split-K ----------
template<bool GELU>
__global__ __launch_bounds__(256) void gemm_nt(const float* __restrict__ A,
        const float* __restrict__ W, const float* __restrict__ bias,
        float* __restrict__ C, int M, int N, int K){
    __shared__ float As[16][68];
    __shared__ float Bs[16][68];
    int m0 = blockIdx.y*64, n0 = blockIdx.x*64;
    int z = blockIdx.z, nz = gridDim.z;
    int ks = K/nz, kbeg = z*ks;
    int tid = threadIdx.x;
    int tm = tid>>2, tk4 = (tid&3)*4;
    int ty = tid>>4, tx = tid&15;
    float acc[4][4];
#pragma unroll
    for (int i = 0; i < 4; i++)
#pragma unroll
        for (int j = 0; j < 4; j++) acc[i][j] = 0.f;
    for (int k0 = kbeg; k0 < kbeg + ks; k0 += 16){
        float4 a4 = *(const float4*)(A + (m0+tm)*K + k0 + tk4);
        float4 w4 = *(const float4*)(W + (n0+tm)*K + k0 + tk4);
        As[tk4+0][tm] = a4.x; As[tk4+1][tm] = a4.y; As[tk4+2][tm] = a4.z; As[tk4+3][tm] = a4.w;
        Bs[tk4+0][tm] = w4.x; Bs[tk4+1][tm] = w4.y; Bs[tk4+2][tm] = w4.z; Bs[tk4+3][tm] = w4.w;
        __syncthreads();
#pragma unroll
        for (int kk = 0; kk < 16; kk++){
            float4 av = *(const float4*)&As[kk][ty*4];
            float4 wv = *(const float4*)&Bs[kk][tx*4];
            acc[0][0] = fmaf(av.x, wv.x, acc[0][0]); acc[0][1] = fmaf(av.x, wv.y, acc[0][1]);
            acc[0][2] = fmaf(av.x, wv.z, acc[0][2]); acc[0][3] = fmaf(av.x, wv.w, acc[0][3]);
            acc[1][0] = fmaf(av.y, wv.x, acc[1][0]); acc[1][1] = fmaf(av.y, wv.y, acc[1][1]);
            acc[1][2] = fmaf(av.y, wv.z, acc[1][2]); acc[1][3] = fmaf(av.y, wv.w, acc[1][3]);
            acc[2][0] = fmaf(av.z, wv.x, acc[2][0]); acc[2][1] = fmaf(av.z, wv.y, acc[2][1]);
            acc[2][2] = fmaf(av.z, wv.z, acc[2][2]); acc[2][3] = fmaf(av.z, wv.w, acc[2][3]);
            acc[3][0] = fmaf(av.w, wv.x, acc[3][0]); acc[3][1] = fmaf(av.w, wv.y, acc[3][1]);
            acc[3][2] = fmaf(av.w, wv.z, acc[3][2]); acc[3][3] = fmaf(av.w, wv.w, acc[3][3]);
        }
        __syncthreads();
    }
#pragma unroll
    for (int i = 0; i < 4; i++){
        int m = m0 + ty*4 + i;
#pragma unroll
        for (int j = 0; j < 4; j++){
            int n = n0 + tx*4 + j;
            float v = acc[i][j];
            if (nz == 1){
                if (bias) v += bias[n];
                if (GELU) v = gelu_f(v);
                C[m*N + n] = v;
            } else {
                C[z*M*N + m*N + n] = v;
            }
        }
    }
}

// ---------- attention (anti-causal mask, faithful to reference) ----------
__global__ __launch_bounds__(256) void attn_kernel(){
    extern __shared__ float sm[];
    float* kt = sm;               // [64][129] transposed K
    float* vs = kt + 64*129;      // [128][64]
    float* qs = vs + 128*64;      // [32][64]
    float* ws = qs + 32*64;       // [8 warps][4][128]
    int bh = blockIdx.x, b = bh>>3, h = bh&7;
    int q0 = blockIdx.y*32;
    int tid = threadIdx.x;
    for (int idx = tid; idx < 8192; idx += 256){
        int k = idx>>6, d = idx&63;
        int base = (b*128 + k)*1536 + h*64 + d;
        kt[d*129 + k] = g_qkv[base + 512];
        vs[k*64 + d]  = g_qkv[base + 1024];
    }
    for (int idx = tid; idx < 2048; idx += 256){
        int r = idx>>6, d = idx&63;
        qs[idx] = g_qkv[(b*128 + q0 + r)*1536 + h*64 + d];
    }
    __syncthreads();
    int warp = tid>>5, lane = tid&31;
    int r0 = warp*4;
    float acc[4][4];
#pragma unroll
    for (int r = 0; r < 4; r++)
#pragma unroll
        for (int s = 0; s < 4; s++) acc[r][s] = 0.f;
#pragma unroll 4
    for (int d = 0; d < 64; d++){
        float k0v = kt[d*129 + lane];
        float k1v = kt[d*129 + 32 + lane];
        float k2v = kt[d*129 + 64 + lane];
        float k3v = kt[d*129 + 96 + lane];
#pragma unroll
        for (int r = 0; r < 4; r++){
            float qv = qs[(r0+r)*64 + d];
            acc[r][0] = fmaf(qv, k0v, acc[r][0]);
            acc[r][1] = fmaf(qv, k1v, acc[r][1]);
            acc[r][2] = fmaf(qv, k2v, acc[r][2]);
            acc[r][3] = fmaf(qv, k3v, acc[r][3]);
        }
    }
#pragma unroll
    for (int r = 0; r < 4; r++){
        int qi = q0 + r0 + r;
        float s[4];
#pragma unroll
        for (int sl = 0; sl < 4; sl++){
            int ki = sl*32 + lane;
            s[sl] = (ki > qi) ? acc[r][sl]*0.125f : NEGMIN;
        }
        float mx = fmaxf(fmaxf(s[0], s[1]), fmaxf(s[2], s[3]));
        mx = warp_max(mx);
        float e[4], sum = 0.f;
#pragma unroll
        for (int sl = 0; sl < 4; sl++){ e[sl] = expf(s[sl] - mx); sum += e[sl]; }
        sum = warp_sum(sum);
        float inv = 1.0f/sum;
#pragma unroll
        for (int sl = 0; sl < 4; sl++)
            ws[(warp*4 + r)*128 + sl*32 + lane] = e[sl]*inv;
    }
    __syncwarp();
    float o0[4] = {0,0,0,0}, o1[4] = {0,0,0,0};
#pragma unroll 4
    for (int k = 0; k < 128; k++){
        float v0 = vs[k*64 + lane];
        float v1 = vs[k*64 + 32 + lane];
#pragma unroll
        for (int r = 0; r < 4; r++){
            float wv = ws[(warp*4 + r)*128 + k];
            o0[r] = fmaf(wv, v0, o0[r]);
            o1[r] = fmaf(wv, v1, o1[r]);
        }
    }
#pragma unroll
    for (int r = 0; r < 4; r++){
        int row = (b*128 + q0 + r0 + r)*512 + h*64;
        g_attn[row + lane]      = o0[r];
        g_attn[row + 32 + lane] = o1[r];
    }
}

// ---------- LayerNorm with fused residual + split-K partial sum + bias ----------
__global__ __launch_bounds__(256) void ln_kernel(float* __restrict__ h,
        const float* __restrict__ p0, const float* __restrict__ p1,
        const float* __restrict__ bias, const float* __restrict__ gw,
        const float* __restrict__ bw){
    __shared__ float red[8];
    __shared__ float bc;
    int tid = threadIdx.x;
    int base = blockIdx.x*512;
    float x0 = h[base+tid]     + p0[base+tid]     + p1[base+tid];
    float x1 = h[base+tid+256] + p0[base+tid+256] + p1[base+tid+256];
    if (bias){ x0 += bias[tid]; x1 += bias[tid+256]; }
    float s = warp_sum(x0 + x1);
    if ((tid&31) == 0) red[tid>>5] = s;
    __syncthreads();
    if (tid == 0){ float t = 0.f; for (int i = 0; i < 8; i++) t += red[i]; bc = t*(1.f/512.f); }
    __syncthreads();
    float mu = bc;
    float d0 = x0 - mu, d1 = x1 - mu;
    float v = warp_sum(d0*d0 + d1*d1);
    if ((tid&31) == 0) red[tid>>5] = v;
    __syncthreads();
    if (tid == 0){ float t = 0.f; for (int i = 0; i < 8; i++) t += red[i]; bc = rsqrtf(t*(1.f/512.f) + LN_EPS); }
    __syncthreads();
    float r = bc;
    h[base+tid]     = d0*r*gw[tid]     + bw[tid];
    h[base+tid+256] = d1*r*gw[tid+256] + bw[tid+256];
}

// ---------- refine: 5 sub-iterations, algebraically rewritten ----------
__global__ __launch_bounds__(256) void refine_kernel(const float* __restrict__ Wr1,
        const float* __restrict__ Wr2, const float* __restrict__ br2,
        float* __restrict__ out, int step){
    __shared__ float ctx[512];
    __shared__ float cur[32];
    __shared__ float hid[2048];
    __shared__ float part[8][32];
    int b = blockIdx.x, tid = threadIdx.x;
    int ptr = 120 + step;
    int row = b*128 + ptr - 1;
    for (int i = tid; i < 512; i += 256) ctx[i] = g_h[row*512 + i];
    if (tid < 32) cur[tid] = g_buf[row*32 + tid];
    __syncthreads();
    float basev[8];
#pragma unroll
    for (int c = 0; c < 8; c++){
        int j = c*256 + tid;
        const float* wr = Wr1 + j*1024 + 512;
        float a0 = 0.f, a1 = 0.f, a2 = 0.f, a3 = 0.f;
        for (int k = 0; k < 512; k += 4){
            a0 = fmaf(wr[k],   ctx[k],   a0);
            a1 = fmaf(wr[k+1], ctx[k+1], a1);
            a2 = fmaf(wr[k+2], ctx[k+2], a2);
            a3 = fmaf(wr[k+3], ctx[k+3], a3);
        }
        basev[c] = a0 + a1 + a2 + a3 + g_c1[j];
    }
    int li = tid & 31, lc = tid >> 5;
    for (int it = 0; it < 5; it++){
        __syncthreads();
#pragma unroll
        for (int c = 0; c < 8; c++){
            int j = c*256 + tid;
            const float* mp = g_M + j*32;
            float p = basev[c];
#pragma unroll
            for (int i = 0; i < 32; i++) p = fmaf(mp[i], cur[i], p);
            hid[j] = gelu_f(p);
        }
        __syncthreads();
        const float* w2 = Wr2 + li*2048 + lc*256;
        const float* hp = hid + lc*256;
        float p0 = 0.f, p1 = 0.f;
        for (int k = 0; k < 256; k += 2){
            p0 = fmaf(w2[k],   hp[k],   p0);
            p1 = fmaf(w2[k+1], hp[k+1], p1);
        }
        part[lc][li] = p0 + p1;
        __syncthreads();
        if (tid < 32){
            float d = br2[tid];
#pragma unroll
            for (int c = 0; c < 8; c++) d += part[c][tid];
            cur[tid] += d;
        }
    }
    __syncthreads();
    if (tid < 32){
        float v = cur[tid];
        g_buf[(b*128 + ptr)*32 + tid] = v;
        out[(b*8 + step)*32 + tid] = v;
    }
}

// ---------- host ----------
#define ATTN_SMEM (22592*4)

extern "C" void kernel_launch(void* const* d_in, const int* in_sizes, int n_in,
                              void* d_out, int out_size){
    const float* hist  = (const float*)d_in[0];
    const float* W_emb = (const float*)d_in[2];
    const float* b_emb = (const float*)d_in[3];
    const float* Wq    = (const float*)d_in[4];
    const float* Wk    = (const float*)d_in[5];
    const float* Wv    = (const float*)d_in[6];
    const float* Wo    = (const float*)d_in[7];
    const float* ln1g  = (const float*)d_in[8];
    const float* ln1b  = (const float*)d_in[9];
    const float* W1    = (const float*)d_in[10];
    const float* b1    = (const float*)d_in[11];
    const float* W2    = (const float*)d_in[12];
    const float* b2    = (const float*)d_in[13];
    const float* ln2g  = (const float*)d_in[14];
    const float* ln2b  = (const float*)d_in[15];
    const float* Wr1   = (const float*)d_in[16];
    const float* br1   = (const float*)d_in[17];
    const float* Wr2   = (const float*)d_in[18];
    const float* br2   = (const float*)d_in[19];
    float* out = (float*)d_out;

    cudaFuncSetAttribute(attn_kernel, cudaFuncAttributeMaxDynamicSharedMemorySize, ATTN_SMEM);

    float *ph, *pqkv2, *pattn, *pt2, *pff, *pwqkv;
    cudaGetSymbolAddress((void**)&ph,    g_h);
    cudaGetSymbolAddress((void**)&pqkv2, g_qkv);
    cudaGetSymbolAddress((void**)&pattn, g_attn);
    cudaGetSymbolAddress((void**)&pt2,   g_t2);
    cudaGetSymbolAddress((void**)&pff,   g_ff);
    cudaGetSymbolAddress((void**)&pwqkv, g_wqkv);

    init_buf_kernel<<<(4*128*32 + 255)/256, 256>>>(hist);
    pack_qkv_kernel<<<(4*1536*512 + 255)/256, 256>>>(Wq, Wk, Wv);
    prep_pe_kernel<<<(128*512 + 255)/256, 256>>>();
    prep_M_kernel<<<2048, 32>>>(Wr1, W_emb, b_emb, br1);

    for (int step = 0; step < 8; step++){
        embed_kernel<<<512, 512>>>(W_emb, b_emb);
        for (int l = 0; l < 4; l++){
            gemm_nt<false><<<dim3(24,8,1), 256>>>(ph, pwqkv + l*1536*512, nullptr,
                                                  pqkv2, 512, 1536, 512);
            attn_kernel<<<dim3(32,4), 256, ATTN_SMEM>>>();
            gemm_nt<false><<<dim3(8,8,2), 256>>>(pattn, Wo + l*512*512, nullptr,
                                                 pt2, 512, 512, 512);
            ln_kernel<<<512, 256>>>(ph, pt2, pt2 + 512*512, nullptr,
                                    ln1g + l*512, ln1b + l*512);
            gemm_nt<true><<<dim3(32,8,1), 256>>>(ph, W1 + l*2048*512, b1 + l*2048,
                                                 pff, 512, 2048, 512);
            gemm_nt<false><<<dim3(8,8,2), 256>>>(pff, W2 + l*512*2048, nullptr,
                                                 pt2, 512, 512, 2048);
            ln_kernel<<<512, 256>>>(ph, pt2, pt2 + 512*512, b2 + l*512,
                                    ln2g + l*512, ln2b + l*512);
        }
        refine_kernel<<<4, 256>>>(Wr1, Wr2, br2, out, step);
    }
}

// round 4
// speedup vs baseline: 1.3634x; 1.3634x over previous
#include <cuda_runtime.h>
#include <cuda_bf16.h>
#include <math.h>
#include <stdint.h>

#define NEGMIN (-3.4028234663852886e38f)
#define EMB_SCALE 22.627416997969522f
#define LN_EPS 1e-5f

// ---------- device scratch ----------
__device__ float g_buf [4*128*32];
__device__ float g_h   [4*128*512];
__device__ float g_qkv [4*128*1536];
__device__ float g_attn[4*128*512];
__device__ float g_t2  [4*512*512];
__device__ float g_ff  [512*2048];
__device__ float g_pe  [128*512];
__device__ float g_M   [2048*32];
__device__ float g_c1  [2048];
// split weights: per layer block of 3145728 elems: qkv[1536x512]@0, wo[512x512]@786432,
// w1[2048x512]@1048576, w2[512x2048]@2097152
__device__ __nv_bfloat16 g_whi[4*3145728];
__device__ __nv_bfloat16 g_wlo[4*3145728];

__device__ __forceinline__ float warp_sum(float v){
    v += __shfl_xor_sync(0xffffffffu, v, 16);
    v += __shfl_xor_sync(0xffffffffu, v, 8);
    v += __shfl_xor_sync(0xffffffffu, v, 4);
    v += __shfl_xor_sync(0xffffffffu, v, 2);
    v += __shfl_xor_sync(0xffffffffu, v, 1);
    return v;
}
__device__ __forceinline__ float warp_max(float v){
    v = fmaxf(v, __shfl_xor_sync(0xffffffffu, v, 16));
    v = fmaxf(v, __shfl_xor_sync(0xffffffffu, v, 8));
    v = fmaxf(v, __shfl_xor_sync(0xffffffffu, v, 4));
    v = fmaxf(v, __shfl_xor_sync(0xffffffffu, v, 2));
    v = fmaxf(v, __shfl_xor_sync(0xffffffffu, v, 1));
    return v;
}
__device__ __forceinline__ float gelu_f(float x){
    float x3 = x*x*x;
    return 0.5f*x*(1.0f + tanhf(0.7978845608028654f*(x + 0.044715f*x3)));
}
static __device__ __forceinline__ uint32_t smem_u32(const void* p){
    uint32_t a;
    asm("{ .reg .u64 t; cvta.to.shared.u64 t, %1; cvt.u32.u64 %0, t; }" : "=r"(a) : "l"(p));
    return a;
}
static __device__ __forceinline__ void ldm4(uint32_t* r, uint32_t addr){
    asm volatile("ldmatrix.sync.aligned.m8n8.x4.shared.b16 {%0,%1,%2,%3}, [%4];"
        : "=r"(r[0]),"=r"(r[1]),"=r"(r[2]),"=r"(r[3]) : "r"(addr));
}
static __device__ __forceinline__ void mma_bf16(float* c, const uint32_t* a, const uint32_t* b){
    asm volatile("mma.sync.aligned.m16n8k16.row.col.f32.bf16.bf16.f32 "
        "{%0,%1,%2,%3}, {%4,%5,%6,%7}, {%8,%9}, {%0,%1,%2,%3};"
        : "+f"(c[0]),"+f"(c[1]),"+f"(c[2]),"+f"(c[3])
        : "r"(a[0]),"r"(a[1]),"r"(a[2]),"r"(a[3]), "r"(b[0]),"r"(b[1]));
}
static __device__ __forceinline__ uint32_t b2u(__nv_bfloat162 h){
    return *(uint32_t*)&h;
}

// ---------- weight split prep (fp32 -> bf16 hi/lo), one-time ----------
__global__ void split_weights_kernel(const float* __restrict__ Wq, const float* __restrict__ Wk,
        const float* __restrict__ Wv, const float* __restrict__ Wo,
        const float* __restrict__ W1, const float* __restrict__ W2){
    int i4 = blockIdx.x*blockDim.x + threadIdx.x;
    if (i4 >= 3145728) return;              // 12.58M / 4
    int idx = i4*4;
    int l = idx / 3145728;
    int r = idx - l*3145728;
    const float* src;
    if (r < 786432){
        int n = r>>9, k = r&511;
        if (n < 512)       src = Wq + ((size_t)l*512 + n      )*512 + k;
        else if (n < 1024) src = Wk + ((size_t)l*512 + n - 512)*512 + k;
        else               src = Wv + ((size_t)l*512 + n -1024)*512 + k;
    } else if (r < 1048576){
        src = Wo + (size_t)l*262144 + (r - 786432);
    } else if (r < 2097152){
        src = W1 + (size_t)l*1048576 + (r - 1048576);
    } else {
        src = W2 + (size_t)l*1048576 + (r - 2097152);
    }
    float4 v = *(const float4*)src;
    __nv_bfloat162 h0 = __floats2bfloat162_rn(v.x, v.y);
    __nv_bfloat162 h1 = __floats2bfloat162_rn(v.z, v.w);
    float lx = v.x - __bfloat162float(h0.x);
    float ly = v.y - __bfloat162float(h0.y);
    float lz = v.z - __bfloat162float(h1.x);
    float lw = v.w - __bfloat162float(h1.y);
    __nv_bfloat162 e0 = __floats2bfloat162_rn(lx, ly);
    __nv_bfloat162 e1 = __floats2bfloat162_rn(lz, lw);
    *(uint2*)(g_whi + idx) = make_uint2(b2u(h0), b2u(h1));
    *(uint2*)(g_wlo + idx) = make_uint2(b2u(e0), b2u(e1));
}

// ---------- tensor-core GEMM: C[M,N] = A[M,K] @ W[N,K]^T (bf16 2-split, fp32 acc) ----------
// CTA tile 128x64, 8 warps (4m x 2n, warp tile 32x32), K-chunk 32, double-buffered.
// smem per buffer: Ahi[128 rows x 80B] 10240, Alo +10240, Whi @20480 [64x80B] 5120, Wlo @25600. BUF=30720.
#define GT_SMEM (2*30720)

template<bool GELU>
__global__ __launch_bounds__(256) void gemm_tc(const float* __restrict__ A,
        const __nv_bfloat16* __restrict__ Whi, const __nv_bfloat16* __restrict__ Wlo,
        const float* __restrict__ bias, float* __restrict__ C, int M, int N, int K){
    extern __shared__ char sm[];
    uint32_t sb = smem_u32(sm);
    int tid = threadIdx.x, wid = tid>>5, lane = tid&31;
    int n0 = blockIdx.x*64, m0 = blockIdx.y*128;
    int z = blockIdx.z, nz = gridDim.z;
    int ks = K/nz, kbeg = z*ks, CH = ks/32;
    int wm = (wid>>1)*32, wn = (wid&1)*32;

    float acc[2][4][4];
#pragma unroll
    for (int a = 0; a < 2; a++)
#pragma unroll
        for (int b = 0; b < 4; b++)
#pragma unroll
            for (int c = 0; c < 4; c++) acc[a][b][c] = 0.f;

    float4 aR[4]; uint4 wR0, wR1;
    int arow[4], akq[4];
#pragma unroll
    for (int j = 0; j < 4; j++){ int g = tid + 256*j; arow[j] = g>>3; akq[j] = g&7; }
    int wrow = tid>>2, wk16 = tid&3;

    // ldmatrix base addresses (per warp/lane)
    uint32_t a_addr = (uint32_t)((wm + (lane&15))*80 + ((lane>>4)<<4));
    uint32_t b_addr = (uint32_t)(20480 + (wn + (lane&7) + ((lane>>4)<<3))*80 + ((lane&8)<<1));

    // prologue: load + stage chunk 0
    {
        int kk = kbeg;
#pragma unroll
        for (int j = 0; j < 4; j++)
            aR[j] = *(const float4*)(A + (size_t)(m0+arow[j])*K + kk + akq[j]*4);
        wR0 = *(const uint4*)(Whi + (size_t)(n0+wrow)*K + kk + wk16*8);
        wR1 = *(const uint4*)(Wlo + (size_t)(n0+wrow)*K + kk + wk16*8);
    }
    for (int c = 0; c < CH; c++){
        // stage current regs into buf (c&1)
        {
            char* bp = sm + (c&1)*30720;
#pragma unroll
            for (int j = 0; j < 4; j++){
                float4 v = aR[j];
                __nv_bfloat162 h0 = __floats2bfloat162_rn(v.x, v.y);
                __nv_bfloat162 h1 = __floats2bfloat162_rn(v.z, v.w);
                float lx = v.x - __bfloat162float(h0.x);
                float ly = v.y - __bfloat162float(h0.y);
                float lz = v.z - __bfloat162float(h1.x);
                float lw = v.w - __bfloat162float(h1.y);
                __nv_bfloat162 e0 = __floats2bfloat162_rn(lx, ly);
                __nv_bfloat162 e1 = __floats2bfloat162_rn(lz, lw);
                char* p = bp + arow[j]*80 + akq[j]*8;
                *(uint2*)p           = make_uint2(b2u(h0), b2u(h1));
                *(uint2*)(p + 10240) = make_uint2(b2u(e0), b2u(e1));
            }
            char* q = bp + 20480 + wrow*80 + wk16*16;
            *(uint4*)q          = wR0;
            *(uint4*)(q + 5120) = wR1;
        }
        __syncthreads();
        // prefetch next chunk
        if (c+1 < CH){
            int kk = kbeg + (c+1)*32;
#pragma unroll
            for (int j = 0; j < 4; j++)
                aR[j] = *(const float4*)(A + (size_t)(m0+arow[j])*K + kk + akq[j]*4);
            wR0 = *(const uint4*)(Whi + (size_t)(n0+wrow)*K + kk + wk16*8);
            wR1 = *(const uint4*)(Wlo + (size_t)(n0+wrow)*K + kk + wk16*8);
        }
        // compute from buf (c&1)
        {
            uint32_t bufb = sb + (c&1)*30720;
#pragma unroll
            for (int s = 0; s < 2; s++){
                uint32_t ah[2][4], al[2][4], bh[2][4], bl[2][4];
                ldm4(ah[0], bufb + a_addr + s*32);
                ldm4(ah[1], bufb + a_addr + 16*80 + s*32);
                ldm4(al[0], bufb + a_addr + 10240 + s*32);
                ldm4(al[1], bufb + a_addr + 10240 + 16*80 + s*32);
                ldm4(bh[0], bufb + b_addr + s*32);
                ldm4(bh[1], bufb + b_addr + 16*80 + s*32);
                ldm4(bl[0], bufb + b_addr + 5120 + s*32);
                ldm4(bl[1], bufb + b_addr + 5120 + 16*80 + s*32);
#pragma unroll
                for (int mt = 0; mt < 2; mt++)
#pragma unroll
                    for (int nf = 0; nf < 4; nf++){
                        const uint32_t* Bh = &bh[nf>>1][(nf&1)*2];
                        const uint32_t* Bl = &bl[nf>>1][(nf&1)*2];
                        mma_bf16(acc[mt][nf], ah[mt], Bh);
                        mma_bf16(acc[mt][nf], ah[mt], Bl);
                        mma_bf16(acc[mt][nf], al[mt], Bh);
                    }
            }
        }
        __syncthreads();
    }
    // epilogue
#pragma unroll
    for (int mt = 0; mt < 2; mt++){
        int r0 = m0 + wm + mt*16 + (lane>>2);
#pragma unroll
        for (int nf = 0; nf < 4; nf++){
            int col = n0 + wn + nf*8 + (lane&3)*2;
            float v0 = acc[mt][nf][0], v1 = acc[mt][nf][1];
            float v2 = acc[mt][nf][2], v3 = acc[mt][nf][3];
            if (nz == 1){
                if (bias){
                    float b0 = bias[col], b1 = bias[col+1];
                    v0 += b0; v1 += b1; v2 += b0; v3 += b1;
                }
                if (GELU){ v0 = gelu_f(v0); v1 = gelu_f(v1); v2 = gelu_f(v2); v3 = gelu_f(v3); }
                *(float2*)(C + (size_t)r0*N + col)     = make_float2(v0, v1);
                *(float2*)(C + (size_t)(r0+8)*N + col) = make_float2(v2, v3);
            } else {
                size_t zo = (size_t)z*M*N;
                *(float2*)(C + zo + (size_t)r0*N + col)     = make_float2(v0, v1);
                *(float2*)(C + zo + (size_t)(r0+8)*N + col) = make_float2(v2, v3);
            }
        }
    }
}

// ---------- prep kernels ----------
__global__ void init_buf_kernel(const float* __restrict__ hist){
    int idx = blockIdx.x*blockDim.x + threadIdx.x;
    if (idx >= 4*128*32) return;
    int i = idx & 31, t = (idx>>5)&127, b = idx>>12;
    g_buf[idx] = (t < 120) ? hist[(b*120 + t)*32 + i] : 0.0f;
}
__global__ void prep_pe_kernel(){
    int idx = blockIdx.x*blockDim.x + threadIdx.x;
    if (idx >= 128*512) return;
    int d = idx & 511, t = idx>>9;
    double freq = exp((double)(d & ~1) * (-9.210340371976184/512.0));
    double ang = (double)t * freq;
    g_pe[idx] = (float)((d & 1) ? cos(ang) : sin(ang));
}
__global__ void prep_M_kernel(const float* __restrict__ Wr1, const float* __restrict__ W_emb,
                              const float* __restrict__ b_emb, const float* __restrict__ br1){
    int j = blockIdx.x, lane = threadIdx.x;
    const float* wr = Wr1 + j*1024;
    float a = 0.f;
    for (int k = 0; k < 512; k++) a = fmaf(wr[k], W_emb[k*32 + lane], a);
    g_M[j*32 + lane] = a * EMB_SCALE;
    float c = 0.f;
    for (int k = lane; k < 512; k += 32) c = fmaf(wr[k], b_emb[k], c);
    c = warp_sum(c);
    if (lane == 0) g_c1[j] = c * EMB_SCALE + br1[j];
}

// ---------- embedding ----------
__global__ __launch_bounds__(512) void embed_kernel(const float* __restrict__ W_emb,
                                                    const float* __restrict__ b_emb){
    __shared__ float xs[32];
    int bt = blockIdx.x, t = bt & 127;
    if (threadIdx.x < 32) xs[threadIdx.x] = g_buf[bt*32 + threadIdx.x];
    __syncthreads();
    int d = threadIdx.x;
    const float* wr = W_emb + d*32;
    float acc = 0.f;
#pragma unroll
    for (int i = 0; i < 32; i++) acc = fmaf(wr[i], xs[i], acc);
    g_h[bt*512 + d] = (acc + b_emb[d]) * EMB_SCALE + g_pe[t*512 + d];
}

// ---------- attention (anti-causal mask, faithful to reference) ----------
__global__ __launch_bounds__(256) void attn_kernel(){
    extern __shared__ float smf[];
    float* kt = smf;              // [64][129]
    float* vs = kt + 64*129;      // [128][64]
    float* qs = vs + 128*64;      // [32][64]
    float* ws = qs + 32*64;       // [8][4][128]
    int bh = blockIdx.x, b = bh>>3, h = bh&7;
    int q0 = blockIdx.y*32;
    int tid = threadIdx.x;
    for (int idx = tid; idx < 8192; idx += 256){
        int k = idx>>6, d = idx&63;
        int base = (b*128 + k)*1536 + h*64 + d;
        kt[d*129 + k] = g_qkv[base + 512];
        vs[k*64 + d]  = g_qkv[base + 1024];
    }
    for (int idx = tid; idx < 2048; idx += 256){
        int r = idx>>6, d = idx&63;
        qs[idx] = g_qkv[(b*128 + q0 + r)*1536 + h*64 + d];
    }
    __syncthreads();
    int warp = tid>>5, lane = tid&31;
    int r0 = warp*4;
    float acc[4][4];
#pragma unroll
    for (int r = 0; r < 4; r++)
#pragma unroll
        for (int s = 0; s < 4; s++) acc[r][s] = 0.f;
#pragma unroll 4
    for (int d = 0; d < 64; d++){
        float k0v = kt[d*129 + lane];
        float k1v = kt[d*129 + 32 + lane];
        float k2v = kt[d*129 + 64 + lane];
        float k3v = kt[d*129 + 96 + lane];
#pragma unroll
        for (int r = 0; r < 4; r++){
            float qv = qs[(r0+r)*64 + d];
            acc[r][0] = fmaf(qv, k0v, acc[r][0]);
            acc[r][1] = fmaf(qv, k1v, acc[r][1]);
            acc[r][2] = fmaf(qv, k2v, acc[r][2]);
            acc[r][3] = fmaf(qv, k3v, acc[r][3]);
        }
    }
#pragma unroll
    for (int r = 0; r < 4; r++){
        int qi = q0 + r0 + r;
        float s[4];
#pragma unroll
        for (int sl = 0; sl < 4; sl++){
            int ki = sl*32 + lane;
            s[sl] = (ki > qi) ? acc[r][sl]*0.125f : NEGMIN;
        }
        float mx = fmaxf(fmaxf(s[0], s[1]), fmaxf(s[2], s[3]));
        mx = warp_max(mx);
        float e[4], sum = 0.f;
#pragma unroll
        for (int sl = 0; sl < 4; sl++){ e[sl] = expf(s[sl] - mx); sum += e[sl]; }
        sum = warp_sum(sum);
        float inv = 1.0f/sum;
#pragma unroll
        for (int sl = 0; sl < 4; sl++)
            ws[(warp*4 + r)*128 + sl*32 + lane] = e[sl]*inv;
    }
    __syncwarp();
    float o0[4] = {0,0,0,0}, o1[4] = {0,0,0,0};
#pragma unroll 4
    for (int k = 0; k < 128; k++){
        float v0 = vs[k*64 + lane];
        float v1 = vs[k*64 + 32 + lane];
#pragma unroll
        for (int r = 0; r < 4; r++){
            float wv = ws[(warp*4 + r)*128 + k];
            o0[r] = fmaf(wv, v0, o0[r]);
            o1[r] = fmaf(wv, v1, o1[r]);
        }
    }
#pragma unroll
    for (int r = 0; r < 4; r++){
        int row = (b*128 + q0 + r0 + r)*512 + h*64;
        g_attn[row + lane]      = o0[r];
        g_attn[row + 32 + lane] = o1[r];
    }
}

// ---------- LayerNorm: residual + 4 split-K partials + optional bias ----------
__global__ __launch_bounds__(256) void ln_kernel(float* __restrict__ h,
        const float* __restrict__ parts, const float* __restrict__ bias,
        const float* __restrict__ gw, const float* __restrict__ bw){
    const int MN = 512*512;
    __shared__ float red[8];
    __shared__ float bc;
    int tid = threadIdx.x;
    int base = blockIdx.x*512;
    float x0 = h[base+tid]     + parts[base+tid]     + parts[MN+base+tid]
             + parts[2*MN+base+tid]     + parts[3*MN+base+tid];
    float x1 = h[base+tid+256] + parts[base+tid+256] + parts[MN+base+tid+256]
             + parts[2*MN+base+tid+256] + parts[3*MN+base+tid+256];
    if (bias){ x0 += bias[tid]; x1 += bias[tid+256]; }
    float s = warp_sum(x0 + x1);
    if ((tid&31) == 0) red[tid>>5] = s;
    __syncthreads();
    if (tid == 0){ float t = 0.f; for (int i = 0; i < 8; i++) t += red[i]; bc = t*(1.f/512.f); }
    __syncthreads();
    float mu = bc;
    float d0 = x0 - mu, d1 = x1 - mu;
    float v = warp_sum(d0*d0 + d1*d1);
    if ((tid&31) == 0) red[tid>>5] = v;
    __syncthreads();
    if (tid == 0){ float t = 0.f; for (int i = 0; i < 8; i++) t += red[i]; bc = rsqrtf(t*(1.f/512.f) + LN_EPS); }
    __syncthreads();
    float r = bc;
    h[base+tid]     = d0*r*gw[tid]     + bw[tid];
    h[base+tid+256] = d1*r*gw[tid+256] + bw[tid+256];
}

// ---------- refine ----------
__global__ __launch_bounds__(256) void refine_kernel(const float* __restrict__ Wr1,
        const float* __restrict__ Wr2, const float* __restrict__ br2,
        float* __restrict__ out, int step){
    __shared__ float ctx[512];
    __shared__ float cur[32];
    __shared__ float hid[2048];
    __shared__ float part[8][32];
    int b = blockIdx.x, tid = threadIdx.x;
    int ptr = 120 + step;
    int row = b*128 + ptr - 1;
    for (int i = tid; i < 512; i += 256) ctx[i] = g_h[row*512 + i];
    if (tid < 32) cur[tid] = g_buf[row*32 + tid];
    __syncthreads();
    float basev[8];
#pragma unroll
    for (int c = 0; c < 8; c++){
        int j = c*256 + tid;
        const float* wr = Wr1 + j*1024 + 512;
        float a0 = 0.f, a1 = 0.f, a2 = 0.f, a3 = 0.f;
        for (int k = 0; k < 512; k += 4){
            a0 = fmaf(wr[k],   ctx[k],   a0);
            a1 = fmaf(wr[k+1], ctx[k+1], a1);
            a2 = fmaf(wr[k+2], ctx[k+2], a2);
            a3 = fmaf(wr[k+3], ctx[k+3], a3);
        }
        basev[c] = a0 + a1 + a2 + a3 + g_c1[j];
    }
    int li = tid & 31, lc = tid >> 5;
    for (int it = 0; it < 5; it++){
        __syncthreads();
#pragma unroll
        for (int c = 0; c < 8; c++){
            int j = c*256 + tid;
            const float* mp = g_M + j*32;
            float p = basev[c];
#pragma unroll
            for (int i = 0; i < 32; i++) p = fmaf(mp[i], cur[i], p);
            hid[j] = gelu_f(p);
        }
        __syncthreads();
        const float* w2 = Wr2 + li*2048 + lc*256;
        const float* hp = hid + lc*256;
        float p0 = 0.f, p1 = 0.f;
        for (int k = 0; k < 256; k += 2){
            p0 = fmaf(w2[k],   hp[k],   p0);
            p1 = fmaf(w2[k+1], hp[k+1], p1);
        }
        part[lc][li] = p0 + p1;
        __syncthreads();
        if (tid < 32){
            float d = br2[tid];
#pragma unroll
            for (int c = 0; c < 8; c++) d += part[c][tid];
            cur[tid] += d;
        }
    }
    __syncthreads();
    if (tid < 32){
        float v = cur[tid];
        g_buf[(b*128 + ptr)*32 + tid] = v;
        out[(b*8 + step)*32 + tid] = v;
    }
}

// ---------- host ----------
#define ATTN_SMEM (22592*4)

extern "C" void kernel_launch(void* const* d_in, const int* in_sizes, int n_in,
                              void* d_out, int out_size){
    const float* hist  = (const float*)d_in[0];
    const float* W_emb = (const float*)d_in[2];
    const float* b_emb = (const float*)d_in[3];
    const float* Wq    = (const float*)d_in[4];
    const float* Wk    = (const float*)d_in[5];
    const float* Wv    = (const float*)d_in[6];
    const float* Wo    = (const float*)d_in[7];
    const float* ln1g  = (const float*)d_in[8];
    const float* ln1b  = (const float*)d_in[9];
    const float* W1    = (const float*)d_in[10];
    const float* b1    = (const float*)d_in[11];
    const float* W2    = (const float*)d_in[12];
    const float* b2    = (const float*)d_in[13];
    const float* ln2g  = (const float*)d_in[14];
    const float* ln2b  = (const float*)d_in[15];
    const float* Wr1   = (const float*)d_in[16];
    const float* br1   = (const float*)d_in[17];
    const float* Wr2   = (const float*)d_in[18];
    const float* br2   = (const float*)d_in[19];
    float* out = (float*)d_out;

    cudaFuncSetAttribute(attn_kernel, cudaFuncAttributeMaxDynamicSharedMemorySize, ATTN_SMEM);
    cudaFuncSetAttribute(gemm_tc<false>, cudaFuncAttributeMaxDynamicSharedMemorySize, GT_SMEM);
    cudaFuncSetAttribute(gemm_tc<true>,  cudaFuncAttributeMaxDynamicSharedMemorySize, GT_SMEM);

    float *ph, *pqkv2, *pattn, *pt2, *pff;
    __nv_bfloat16 *pwhi, *pwlo;
    cudaGetSymbolAddress((void**)&ph,    g_h);
    cudaGetSymbolAddress((void**)&pqkv2, g_qkv);
    cudaGetSymbolAddress((void**)&pattn, g_attn);
    cudaGetSymbolAddress((void**)&pt2,   g_t2);
    cudaGetSymbolAddress((void**)&pff,   g_ff);
    cudaGetSymbolAddress((void**)&pwhi,  g_whi);
    cudaGetSymbolAddress((void**)&pwlo,  g_wlo);

    init_buf_kernel<<<(4*128*32 + 255)/256, 256>>>(hist);
    split_weights_kernel<<<(3145728 + 255)/256, 256>>>(Wq, Wk, Wv, Wo, W1, W2);
    prep_pe_kernel<<<(128*512 + 255)/256, 256>>>();
    prep_M_kernel<<<2048, 32>>>(Wr1, W_emb, b_emb, br1);

    for (int step = 0; step < 8; step++){
        embed_kernel<<<512, 512>>>(W_emb, b_emb);
        for (int l = 0; l < 4; l++){
            size_t LB = (size_t)l*3145728;
            gemm_tc<false><<<dim3(24,4,1), 256, GT_SMEM>>>(ph, pwhi+LB, pwlo+LB,
                    nullptr, pqkv2, 512, 1536, 512);
            attn_kernel<<<dim3(32,4), 256, ATTN_SMEM>>>();
            gemm_tc<false><<<dim3(8,4,4), 256, GT_SMEM>>>(pattn, pwhi+LB+786432, pwlo+LB+786432,
                    nullptr, pt2, 512, 512, 512);
            ln_kernel<<<512, 256>>>(ph, pt2, nullptr, ln1g + l*512, ln1b + l*512);
            gemm_tc<true><<<dim3(32,4,1), 256, GT_SMEM>>>(ph, pwhi+LB+1048576, pwlo+LB+1048576,
                    b1 + l*2048, pff, 512, 2048, 512);
            gemm_tc<false><<<dim3(8,4,4), 256, GT_SMEM>>>(pff, pwhi+LB+2097152, pwlo+LB+2097152,
                    nullptr, pt2, 512, 512, 2048);
            ln_kernel<<<512, 256>>>(ph, pt2, b2 + l*512, ln2g + l*512, ln2b + l*512);
        }
        refine_kernel<<<4, 256>>>(Wr1, Wr2, br2, out, step);
    }
}

// round 5
// speedup vs baseline: 3.9593x; 2.9040x over previous
#include <cuda_runtime.h>
#include <cuda_bf16.h>
#include <math.h>
#include <stdint.h>

#define NEGMIN (-3.4028234663852886e38f)
#define EMB_SCALE 22.627416997969522f
#define LN_EPS 1e-5f

// ---------- device scratch ----------
__device__ float g_buf [4*128*32];
__device__ float g_h   [4*128*512];
__device__ float g_qkv [4*128*1536];
__device__ float g_t2  [4*512*512];
__device__ float g_pe  [128*512];
__device__ float g_M   [32*2048];       // TRANSPOSED: [k][j]
__device__ float g_c1  [2048];
__device__ float g_basev[4*2048];
__device__ __nv_bfloat16 g_hhi [512*512],  g_hlo [512*512];
__device__ __nv_bfloat16 g_athi[512*512],  g_atlo[512*512];
__device__ __nv_bfloat16 g_ffhi[512*2048], g_fflo[512*2048];
// split weights per layer block of 3145728: qkv@0, wo@786432, w1@1048576, w2@2097152
__device__ __nv_bfloat16 g_whi[4*3145728];
__device__ __nv_bfloat16 g_wlo[4*3145728];

__device__ __forceinline__ float warp_sum(float v){
    v += __shfl_xor_sync(0xffffffffu, v, 16);
    v += __shfl_xor_sync(0xffffffffu, v, 8);
    v += __shfl_xor_sync(0xffffffffu, v, 4);
    v += __shfl_xor_sync(0xffffffffu, v, 2);
    v += __shfl_xor_sync(0xffffffffu, v, 1);
    return v;
}
__device__ __forceinline__ float warp_max(float v){
    v = fmaxf(v, __shfl_xor_sync(0xffffffffu, v, 16));
    v = fmaxf(v, __shfl_xor_sync(0xffffffffu, v, 8));
    v = fmaxf(v, __shfl_xor_sync(0xffffffffu, v, 4));
    v = fmaxf(v, __shfl_xor_sync(0xffffffffu, v, 2));
    v = fmaxf(v, __shfl_xor_sync(0xffffffffu, v, 1));
    return v;
}
__device__ __forceinline__ float gelu_f(float x){
    float x3 = x*x*x;
    return 0.5f*x*(1.0f + tanhf(0.7978845608028654f*(x + 0.044715f*x3)));
}
static __device__ __forceinline__ uint32_t smem_u32(const void* p){
    uint32_t a;
    asm("{ .reg .u64 t; cvta.to.shared.u64 t, %1; cvt.u32.u64 %0, t; }" : "=r"(a) : "l"(p));
    return a;
}
static __device__ __forceinline__ void ldm4(uint32_t* r, uint32_t addr){
    asm volatile("ldmatrix.sync.aligned.m8n8.x4.shared.b16 {%0,%1,%2,%3}, [%4];"
        : "=r"(r[0]),"=r"(r[1]),"=r"(r[2]),"=r"(r[3]) : "r"(addr));
}
static __device__ __forceinline__ void mma_bf16(float* c, const uint32_t* a, const uint32_t* b){
    asm volatile("mma.sync.aligned.m16n8k16.row.col.f32.bf16.bf16.f32 "
        "{%0,%1,%2,%3}, {%4,%5,%6,%7}, {%8,%9}, {%0,%1,%2,%3};"
        : "+f"(c[0]),"+f"(c[1]),"+f"(c[2]),"+f"(c[3])
        : "r"(a[0]),"r"(a[1]),"r"(a[2]),"r"(a[3]), "r"(b[0]),"r"(b[1]));
}
static __device__ __forceinline__ uint32_t b2u(__nv_bfloat162 h){ return *(uint32_t*)&h; }
static __device__ __forceinline__ void split_bf(float v, __nv_bfloat16& hi, __nv_bfloat16& lo){
    hi = __float2bfloat16(v);
    lo = __float2bfloat16(v - __bfloat162float(hi));
}

// ---------- weight split prep ----------
__global__ void split_weights_kernel(const float* __restrict__ Wq, const float* __restrict__ Wk,
        const float* __restrict__ Wv, const float* __restrict__ Wo,
        const float* __restrict__ W1, const float* __restrict__ W2){
    int i4 = blockIdx.x*blockDim.x + threadIdx.x;
    if (i4 >= 3145728) return;
    int idx = i4*4;
    int l = idx / 3145728;
    int r = idx - l*3145728;
    const float* src;
    if (r < 786432){
        int n = r>>9, k = r&511;
        if (n < 512)       src = Wq + ((size_t)l*512 + n      )*512 + k;
        else if (n < 1024) src = Wk + ((size_t)l*512 + n - 512)*512 + k;
        else               src = Wv + ((size_t)l*512 + n -1024)*512 + k;
    } else if (r < 1048576){
        src = Wo + (size_t)l*262144 + (r - 786432);
    } else if (r < 2097152){
        src = W1 + (size_t)l*1048576 + (r - 1048576);
    } else {
        src = W2 + (size_t)l*1048576 + (r - 2097152);
    }
    float4 v = *(const float4*)src;
    __nv_bfloat162 h0 = __floats2bfloat162_rn(v.x, v.y);
    __nv_bfloat162 h1 = __floats2bfloat162_rn(v.z, v.w);
    float lx = v.x - __bfloat162float(h0.x);
    float ly = v.y - __bfloat162float(h0.y);
    float lz = v.z - __bfloat162float(h1.x);
    float lw = v.w - __bfloat162float(h1.y);
    __nv_bfloat162 e0 = __floats2bfloat162_rn(lx, ly);
    __nv_bfloat162 e1 = __floats2bfloat162_rn(lz, lw);
    *(uint2*)(g_whi + idx) = make_uint2(b2u(h0), b2u(h1));
    *(uint2*)(g_wlo + idx) = make_uint2(b2u(e0), b2u(e1));
}

// ---------- tensor-core GEMM: C[M,N] = A[M,K] @ W[N,K]^T (bf16 2-split, fp32 acc) ----------
// CTA tile 128x64, 8 warps (4m x 2n), K-chunk 32, double-buffered smem staging.
// buffer: Ahi[128x80B]@0, Alo@10240, Whi[64x80B]@20480, Wlo@25600; BUF=30720.
#define GT_SMEM (2*30720)
// MODE 0: fp32 C (split-K partials if gridDim.z>1).  MODE 1: bias+gelu -> bf16 hi/lo out.
template<int MODE>
__global__ __launch_bounds__(256) void gemm_tc(
        const __nv_bfloat16* __restrict__ Ahi, const __nv_bfloat16* __restrict__ Alo,
        const __nv_bfloat16* __restrict__ Whi, const __nv_bfloat16* __restrict__ Wlo,
        const float* __restrict__ bias,
        float* __restrict__ C, __nv_bfloat16* __restrict__ Chi, __nv_bfloat16* __restrict__ Clo,
        int M, int N, int K){
    extern __shared__ char sm[];
    uint32_t sb = smem_u32(sm);
    int tid = threadIdx.x, wid = tid>>5, lane = tid&31;
    int n0 = blockIdx.x*64, m0 = blockIdx.y*128;
    int z = blockIdx.z, nz = gridDim.z;
    int ks = K/nz, kbeg = z*ks, CH = ks/32;
    int wm = (wid>>1)*32, wn = (wid&1)*32;

    float acc[2][4][4];
#pragma unroll
    for (int a = 0; a < 2; a++)
#pragma unroll
        for (int b = 0; b < 4; b++)
#pragma unroll
            for (int c = 0; c < 4; c++) acc[a][b][c] = 0.f;

    int ar = tid>>2, aq = tid&3;
    uint4 rAh0, rAh1, rAl0, rAl1, rWh, rWl;
    uint32_t a_addr = (uint32_t)((wm + (lane&15))*80 + ((lane>>4)<<4));
    uint32_t b_addr = (uint32_t)(20480 + (wn + (lane&7) + ((lane>>4)<<3))*80 + ((lane&8)<<1));

    {
        int kk = kbeg;
        size_t o0 = (size_t)(m0+ar)*K + kk + aq*8;
        size_t o1 = (size_t)(m0+ar+64)*K + kk + aq*8;
        size_t ow = (size_t)(n0+ar)*K + kk + aq*8;
        rAh0 = *(const uint4*)(Ahi + o0); rAh1 = *(const uint4*)(Ahi + o1);
        rAl0 = *(const uint4*)(Alo + o0); rAl1 = *(const uint4*)(Alo + o1);
        rWh  = *(const uint4*)(Whi + ow); rWl  = *(const uint4*)(Wlo + ow);
    }
    for (int c = 0; c < CH; c++){
        {
            char* bp = sm + (c&1)*30720;
            uint32_t off = (uint32_t)(ar*80 + aq*16);
            *(uint4*)(bp + off)            = rAh0;
            *(uint4*)(bp + off + 64*80)    = rAh1;
            *(uint4*)(bp + 10240 + off)        = rAl0;
            *(uint4*)(bp + 10240 + off + 64*80)= rAl1;
            *(uint4*)(bp + 20480 + off) = rWh;
            *(uint4*)(bp + 25600 + off) = rWl;
        }
        __syncthreads();
        if (c+1 < CH){
            int kk = kbeg + (c+1)*32;
            size_t o0 = (size_t)(m0+ar)*K + kk + aq*8;
            size_t o1 = (size_t)(m0+ar+64)*K + kk + aq*8;
            size_t ow = (size_t)(n0+ar)*K + kk + aq*8;
            rAh0 = *(const uint4*)(Ahi + o0); rAh1 = *(const uint4*)(Ahi + o1);
            rAl0 = *(const uint4*)(Alo + o0); rAl1 = *(const uint4*)(Alo + o1);
            rWh  = *(const uint4*)(Whi + ow); rWl  = *(const uint4*)(Wlo + ow);
        }
        {
            uint32_t bufb = sb + (c&1)*30720;
#pragma unroll
            for (int s = 0; s < 2; s++){
                uint32_t ah[2][4], al[2][4], bh[2][4], bl[2][4];
                ldm4(ah[0], bufb + a_addr + s*32);
                ldm4(ah[1], bufb + a_addr + 16*80 + s*32);
                ldm4(al[0], bufb + a_addr + 10240 + s*32);
                ldm4(al[1], bufb + a_addr + 10240 + 16*80 + s*32);
                ldm4(bh[0], bufb + b_addr + s*32);
                ldm4(bh[1], bufb + b_addr + 16*80 + s*32);
                ldm4(bl[0], bufb + b_addr + 5120 + s*32);
                ldm4(bl[1], bufb + b_addr + 5120 + 16*80 + s*32);
#pragma unroll
                for (int mt = 0; mt < 2; mt++)
#pragma unroll
                    for (int nf = 0; nf < 4; nf++){
                        const uint32_t* Bh = &bh[nf>>1][(nf&1)*2];
                        const uint32_t* Bl = &bl[nf>>1][(nf&1)*2];
                        mma_bf16(acc[mt][nf], ah[mt], Bh);
                        mma_bf16(acc[mt][nf], ah[mt], Bl);
                        mma_bf16(acc[mt][nf], al[mt], Bh);
                    }
            }
        }
        __syncthreads();
    }
#pragma unroll
    for (int mt = 0; mt < 2; mt++){
        int r0 = m0 + wm + mt*16 + (lane>>2);
#pragma unroll
        for (int nf = 0; nf < 4; nf++){
            int col = n0 + wn + nf*8 + (lane&3)*2;
            float v0 = acc[mt][nf][0], v1 = acc[mt][nf][1];
            float v2 = acc[mt][nf][2], v3 = acc[mt][nf][3];
            if (MODE == 0){
                size_t zo = (nz > 1) ? (size_t)z*M*N : 0;
                *(float2*)(C + zo + (size_t)r0*N + col)     = make_float2(v0, v1);
                *(float2*)(C + zo + (size_t)(r0+8)*N + col) = make_float2(v2, v3);
            } else {
                float b0 = bias[col], b1 = bias[col+1];
                v0 = gelu_f(v0 + b0); v1 = gelu_f(v1 + b1);
                v2 = gelu_f(v2 + b0); v3 = gelu_f(v3 + b1);
                __nv_bfloat162 h0 = __floats2bfloat162_rn(v0, v1);
                __nv_bfloat162 h2 = __floats2bfloat162_rn(v2, v3);
                __nv_bfloat162 l0 = __floats2bfloat162_rn(v0 - __bfloat162float(h0.x),
                                                          v1 - __bfloat162float(h0.y));
                __nv_bfloat162 l2 = __floats2bfloat162_rn(v2 - __bfloat162float(h2.x),
                                                          v3 - __bfloat162float(h2.y));
                *(uint32_t*)(Chi + (size_t)r0*N + col)     = b2u(h0);
                *(uint32_t*)(Chi + (size_t)(r0+8)*N + col) = b2u(h2);
                *(uint32_t*)(Clo + (size_t)r0*N + col)     = b2u(l0);
                *(uint32_t*)(Clo + (size_t)(r0+8)*N + col) = b2u(l2);
            }
        }
    }
}

// ---------- prep kernels ----------
__global__ void init_buf_kernel(const float* __restrict__ hist){
    int idx = blockIdx.x*blockDim.x + threadIdx.x;
    if (idx >= 4*128*32) return;
    int i = idx & 31, t = (idx>>5)&127, b = idx>>12;
    g_buf[idx] = (t < 120) ? hist[(b*120 + t)*32 + i] : 0.0f;
}
__global__ void prep_pe_kernel(){
    int idx = blockIdx.x*blockDim.x + threadIdx.x;
    if (idx >= 128*512) return;
    int d = idx & 511, t = idx>>9;
    double freq = exp((double)(d & ~1) * (-9.210340371976184/512.0));
    double ang = (double)t * freq;
    g_pe[idx] = (float)((d & 1) ? cos(ang) : sin(ang));
}
__global__ void prep_M_kernel(const float* __restrict__ Wr1, const float* __restrict__ W_emb,
                              const float* __restrict__ b_emb, const float* __restrict__ br1){
    int j = blockIdx.x, lane = threadIdx.x;
    const float* wr = Wr1 + j*1024;
    float a = 0.f;
    for (int k = 0; k < 512; k++) a = fmaf(wr[k], W_emb[k*32 + lane], a);
    g_M[lane*2048 + j] = a * EMB_SCALE;     // transposed [k][j]
    float c = 0.f;
    for (int k = lane; k < 512; k += 32) c = fmaf(wr[k], b_emb[k], c);
    c = warp_sum(c);
    if (lane == 0) g_c1[j] = c * EMB_SCALE + br1[j];
}

// ---------- embedding ----------
__global__ __launch_bounds__(512) void embed_kernel(const float* __restrict__ W_emb,
                                                    const float* __restrict__ b_emb){
    __shared__ float xs[32];
    int bt = blockIdx.x, t = bt & 127;
    if (threadIdx.x < 32) xs[threadIdx.x] = g_buf[bt*32 + threadIdx.x];
    __syncthreads();
    int d = threadIdx.x;
    const float* wr = W_emb + d*32;
    float acc = 0.f;
#pragma unroll
    for (int i = 0; i < 32; i++) acc = fmaf(wr[i], xs[i], acc);
    float y = (acc + b_emb[d]) * EMB_SCALE + g_pe[t*512 + d];
    g_h[bt*512 + d] = y;
    __nv_bfloat16 hi, lo; split_bf(y, hi, lo);
    g_hhi[bt*512 + d] = hi; g_hlo[bt*512 + d] = lo;
}

// ---------- attention ----------
__global__ __launch_bounds__(256) void attn_kernel(){
    extern __shared__ float smf[];
    float* kt = smf;
    float* vs = kt + 64*129;
    float* qs = vs + 128*64;
    float* ws = qs + 32*64;
    int bh = blockIdx.x, b = bh>>3, h = bh&7;
    int q0 = blockIdx.y*32;
    int tid = threadIdx.x;
    for (int idx = tid; idx < 8192; idx += 256){
        int k = idx>>6, d = idx&63;
        int base = (b*128 + k)*1536 + h*64 + d;
        kt[d*129 + k] = g_qkv[base + 512];
        vs[k*64 + d]  = g_qkv[base + 1024];
    }
    for (int idx = tid; idx < 2048; idx += 256){
        int r = idx>>6, d = idx&63;
        qs[idx] = g_qkv[(b*128 + q0 + r)*1536 + h*64 + d];
    }
    __syncthreads();
    int warp = tid>>5, lane = tid&31;
    int r0 = warp*4;
    float acc[4][4];
#pragma unroll
    for (int r = 0; r < 4; r++)
#pragma unroll
        for (int s = 0; s < 4; s++) acc[r][s] = 0.f;
#pragma unroll 4
    for (int d = 0; d < 64; d++){
        float k0v = kt[d*129 + lane];
        float k1v = kt[d*129 + 32 + lane];
        float k2v = kt[d*129 + 64 + lane];
        float k3v = kt[d*129 + 96 + lane];
#pragma unroll
        for (int r = 0; r < 4; r++){
            float qv = qs[(r0+r)*64 + d];
            acc[r][0] = fmaf(qv, k0v, acc[r][0]);
            acc[r][1] = fmaf(qv, k1v, acc[r][1]);
            acc[r][2] = fmaf(qv, k2v, acc[r][2]);
            acc[r][3] = fmaf(qv, k3v, acc[r][3]);
        }
    }
#pragma unroll
    for (int r = 0; r < 4; r++){
        int qi = q0 + r0 + r;
        float s[4];
#pragma unroll
        for (int sl = 0; sl < 4; sl++){
            int ki = sl*32 + lane;
            s[sl] = (ki > qi) ? acc[r][sl]*0.125f : NEGMIN;
        }
        float mx = fmaxf(fmaxf(s[0], s[1]), fmaxf(s[2], s[3]));
        mx = warp_max(mx);
        float e[4], sum = 0.f;
#pragma unroll
        for (int sl = 0; sl < 4; sl++){ e[sl] = expf(s[sl] - mx); sum += e[sl]; }
        sum = warp_sum(sum);
        float inv = 1.0f/sum;
#pragma unroll
        for (int sl = 0; sl < 4; sl++)
            ws[(warp*4 + r)*128 + sl*32 + lane] = e[sl]*inv;
    }
    __syncwarp();
    float o0[4] = {0,0,0,0}, o1[4] = {0,0,0,0};
#pragma unroll 4
    for (int k = 0; k < 128; k++){
        float v0 = vs[k*64 + lane];
        float v1 = vs[k*64 + 32 + lane];
#pragma unroll
        for (int r = 0; r < 4; r++){
            float wv = ws[(warp*4 + r)*128 + k];
            o0[r] = fmaf(wv, v0, o0[r]);
            o1[r] = fmaf(wv, v1, o1[r]);
        }
    }
#pragma unroll
    for (int r = 0; r < 4; r++){
        int row = (b*128 + q0 + r0 + r)*512 + h*64;
        __nv_bfloat16 hi, lo;
        split_bf(o0[r], hi, lo);
        g_athi[row + lane] = hi; g_atlo[row + lane] = lo;
        split_bf(o1[r], hi, lo);
        g_athi[row + 32 + lane] = hi; g_atlo[row + 32 + lane] = lo;
    }
}

// ---------- LayerNorm: residual + 4 split-K partials + optional bias; emits fp32 + bf16 hi/lo ----------
__global__ __launch_bounds__(256) void ln_kernel(float* __restrict__ h,
        const float* __restrict__ parts, const float* __restrict__ bias,
        const float* __restrict__ gw, const float* __restrict__ bw){
    const int MN = 512*512;
    __shared__ float red[8];
    __shared__ float bc;
    int tid = threadIdx.x;
    int base = blockIdx.x*512;
    float x0 = h[base+tid]     + parts[base+tid]     + parts[MN+base+tid]
             + parts[2*MN+base+tid]     + parts[3*MN+base+tid];
    float x1 = h[base+tid+256] + parts[base+tid+256] + parts[MN+base+tid+256]
             + parts[2*MN+base+tid+256] + parts[3*MN+base+tid+256];
    if (bias){ x0 += bias[tid]; x1 += bias[tid+256]; }
    float s = warp_sum(x0 + x1);
    if ((tid&31) == 0) red[tid>>5] = s;
    __syncthreads();
    if (tid == 0){ float t = 0.f; for (int i = 0; i < 8; i++) t += red[i]; bc = t*(1.f/512.f); }
    __syncthreads();
    float mu = bc;
    float d0 = x0 - mu, d1 = x1 - mu;
    float v = warp_sum(d0*d0 + d1*d1);
    if ((tid&31) == 0) red[tid>>5] = v;
    __syncthreads();
    if (tid == 0){ float t = 0.f; for (int i = 0; i < 8; i++) t += red[i]; bc = rsqrtf(t*(1.f/512.f) + LN_EPS); }
    __syncthreads();
    float r = bc;
    float y0 = d0*r*gw[tid]     + bw[tid];
    float y1 = d1*r*gw[tid+256] + bw[tid+256];
    h[base+tid]     = y0;
    h[base+tid+256] = y1;
    __nv_bfloat16 hi, lo;
    split_bf(y0, hi, lo); g_hhi[base+tid] = hi;     g_hlo[base+tid] = lo;
    split_bf(y1, hi, lo); g_hhi[base+tid+256] = hi; g_hlo[base+tid+256] = lo;
}

// ---------- refine part 1: basev[b][j] = Wr1_right[j,:] @ h_ctx + c1[j]  (coalesced, 64 blocks) ----------
__global__ __launch_bounds__(256) void refine_basev(const float* __restrict__ Wr1, int step){
    __shared__ float ctx[512];
    int g = blockIdx.x, b = blockIdx.y;
    int tid = threadIdx.x, warp = tid>>5, lane = tid&31;
    int row = b*128 + 119 + step;
    for (int i = tid; i < 512; i += 256) ctx[i] = g_h[row*512 + i];
    __syncthreads();
#pragma unroll
    for (int r = 0; r < 16; r++){
        int j = g*128 + warp*16 + r;
        const float* wr = Wr1 + (size_t)j*1024 + 512;
        float a = 0.f;
#pragma unroll
        for (int k = lane; k < 512; k += 32) a = fmaf(wr[k], ctx[k], a);
        a = warp_sum(a);
        if (lane == 0) g_basev[b*2048 + j] = a + g_c1[j];
    }
}

// ---------- refine part 2: 5 sub-iterations (4 blocks, 512 threads) ----------
__global__ __launch_bounds__(512) void refine_iter(const float* __restrict__ Wr2,
        const float* __restrict__ br2, float* __restrict__ out, int step){
    __shared__ float cur[32];
    __shared__ float basev_s[2048];
    __shared__ float hid[2048];
    __shared__ float outp[32];
    int b = blockIdx.x, tid = threadIdx.x, warp = tid>>5, lane = tid&31;
    int row = b*128 + 119 + step;
    for (int i = tid; i < 2048; i += 512) basev_s[i] = g_basev[b*2048 + i];
    if (tid < 32) cur[tid] = g_buf[row*32 + tid];
    __syncthreads();
    for (int it = 0; it < 5; it++){
        // hid[j] = gelu(basev[j] + Mt[:,j]·cur), thread owns 4 j's (coalesced over Mt rows)
#pragma unroll
        for (int c = 0; c < 4; c++){
            int j = c*512 + tid;
            float p = basev_s[j];
#pragma unroll
            for (int k = 0; k < 32; k++) p = fmaf(g_M[k*2048 + j], cur[k], p);
            hid[j] = gelu_f(p);
        }
        __syncthreads();
        // out[i] = Wr2[i,:]·hid ; 16 warps, 2 outputs each, lanes sweep k (coalesced)
#pragma unroll
        for (int ii = 0; ii < 2; ii++){
            int i = warp*2 + ii;
            const float* w2 = Wr2 + (size_t)i*2048;
            float p = 0.f;
#pragma unroll 8
            for (int k = lane; k < 2048; k += 32) p = fmaf(w2[k], hid[k], p);
            p = warp_sum(p);
            if (lane == 0) outp[i] = p;
        }
        __syncthreads();
        if (tid < 32) cur[tid] += outp[tid] + br2[tid];
        __syncthreads();
    }
    if (tid < 32){
        float v = cur[tid];
        g_buf[(row+1)*32 + tid] = v;
        out[(b*8 + step)*32 + tid] = v;
    }
}

// ---------- host ----------
#define ATTN_SMEM (22592*4)

extern "C" void kernel_launch(void* const* d_in, const int* in_sizes, int n_in,
                              void* d_out, int out_size){
    const float* hist  = (const float*)d_in[0];
    const float* W_emb = (const float*)d_in[2];
    const float* b_emb = (const float*)d_in[3];
    const float* Wq    = (const float*)d_in[4];
    const float* Wk    = (const float*)d_in[5];
    const float* Wv    = (const float*)d_in[6];
    const float* Wo    = (const float*)d_in[7];
    const float* ln1g  = (const float*)d_in[8];
    const float* ln1b  = (const float*)d_in[9];
    const float* W1    = (const float*)d_in[10];
    const float* b1    = (const float*)d_in[11];
    const float* W2    = (const float*)d_in[12];
    const float* b2    = (const float*)d_in[13];
    const float* ln2g  = (const float*)d_in[14];
    const float* ln2b  = (const float*)d_in[15];
    const float* Wr1   = (const float*)d_in[16];
    const float* br1   = (const float*)d_in[17];
    const float* Wr2   = (const float*)d_in[18];
    const float* br2   = (const float*)d_in[19];
    float* out = (float*)d_out;

    cudaFuncSetAttribute(attn_kernel, cudaFuncAttributeMaxDynamicSharedMemorySize, ATTN_SMEM);
    cudaFuncSetAttribute(gemm_tc<0>, cudaFuncAttributeMaxDynamicSharedMemorySize, GT_SMEM);
    cudaFuncSetAttribute(gemm_tc<1>, cudaFuncAttributeMaxDynamicSharedMemorySize, GT_SMEM);

    float *ph, *pqkv2, *pt2;
    __nv_bfloat16 *pwhi, *pwlo, *phhi, *phlo, *pathi, *patlo, *pffhi, *pfflo;
    cudaGetSymbolAddress((void**)&ph,    g_h);
    cudaGetSymbolAddress((void**)&pqkv2, g_qkv);
    cudaGetSymbolAddress((void**)&pt2,   g_t2);
    cudaGetSymbolAddress((void**)&pwhi,  g_whi);
    cudaGetSymbolAddress((void**)&pwlo,  g_wlo);
    cudaGetSymbolAddress((void**)&phhi,  g_hhi);
    cudaGetSymbolAddress((void**)&phlo,  g_hlo);
    cudaGetSymbolAddress((void**)&pathi, g_athi);
    cudaGetSymbolAddress((void**)&patlo, g_atlo);
    cudaGetSymbolAddress((void**)&pffhi, g_ffhi);
    cudaGetSymbolAddress((void**)&pfflo, g_fflo);

    init_buf_kernel<<<(4*128*32 + 255)/256, 256>>>(hist);
    split_weights_kernel<<<(3145728 + 255)/256, 256>>>(Wq, Wk, Wv, Wo, W1, W2);
    prep_pe_kernel<<<(128*512 + 255)/256, 256>>>();
    prep_M_kernel<<<2048, 32>>>(Wr1, W_emb, b_emb, br1);

    for (int step = 0; step < 8; step++){
        embed_kernel<<<512, 512>>>(W_emb, b_emb);
        for (int l = 0; l < 4; l++){
            size_t LB = (size_t)l*3145728;
            gemm_tc<0><<<dim3(24,4,1), 256, GT_SMEM>>>(phhi, phlo, pwhi+LB, pwlo+LB,
                    nullptr, pqkv2, nullptr, nullptr, 512, 1536, 512);
            attn_kernel<<<dim3(32,4), 256, ATTN_SMEM>>>();
            gemm_tc<0><<<dim3(8,4,4), 256, GT_SMEM>>>(pathi, patlo, pwhi+LB+786432, pwlo+LB+786432,
                    nullptr, pt2, nullptr, nullptr, 512, 512, 512);
            ln_kernel<<<512, 256>>>(ph, pt2, nullptr, ln1g + l*512, ln1b + l*512);
            gemm_tc<1><<<dim3(32,4,1), 256, GT_SMEM>>>(phhi, phlo, pwhi+LB+1048576, pwlo+LB+1048576,
                    b1 + l*2048, nullptr, pffhi, pfflo, 512, 2048, 512);
            gemm_tc<0><<<dim3(8,4,4), 256, GT_SMEM>>>(pffhi, pfflo, pwhi+LB+2097152, pwlo+LB+2097152,
                    nullptr, pt2, nullptr, nullptr, 512, 512, 2048);
            ln_kernel<<<512, 256>>>(ph, pt2, b2 + l*512, ln2g + l*512, ln2b + l*512);
        }
        refine_basev<<<dim3(16,4), 256>>>(Wr1, step);
        refine_iter<<<4, 512>>>(Wr2, br2, out, step);
    }
}

// round 6
// speedup vs baseline: 4.0113x; 1.0131x over previous
#include <cuda_runtime.h>
#include <cuda_bf16.h>
#include <math.h>
#include <stdint.h>

#define NEGMIN (-3.4028234663852886e38f)
#define EMB_SCALE 22.627416997969522f
#define LN_EPS 1e-5f

// ---------- device scratch ----------
__device__ float g_buf [4*128*32];
__device__ float g_h   [4*128*512];
__device__ float g_qkv [2*512*1536];    // 2 split-K partial planes
__device__ float g_t2  [4*512*512];
__device__ float g_pe  [128*512];
__device__ float g_M   [32*2048];       // TRANSPOSED: [k][j]
__device__ float g_c1  [2048];
__device__ float g_basev[4*2048];
__device__ __nv_bfloat16 g_hhi [512*512],  g_hlo [512*512];
__device__ __nv_bfloat16 g_athi[512*512],  g_atlo[512*512];
__device__ __nv_bfloat16 g_ffhi[512*2048], g_fflo[512*2048];
// split weights per layer block of 3145728: qkv@0, wo@786432, w1@1048576, w2@2097152
__device__ __nv_bfloat16 g_whi[4*3145728];
__device__ __nv_bfloat16 g_wlo[4*3145728];

__device__ __forceinline__ float warp_sum(float v){
    v += __shfl_xor_sync(0xffffffffu, v, 16);
    v += __shfl_xor_sync(0xffffffffu, v, 8);
    v += __shfl_xor_sync(0xffffffffu, v, 4);
    v += __shfl_xor_sync(0xffffffffu, v, 2);
    v += __shfl_xor_sync(0xffffffffu, v, 1);
    return v;
}
__device__ __forceinline__ float warp_max(float v){
    v = fmaxf(v, __shfl_xor_sync(0xffffffffu, v, 16));
    v = fmaxf(v, __shfl_xor_sync(0xffffffffu, v, 8));
    v = fmaxf(v, __shfl_xor_sync(0xffffffffu, v, 4));
    v = fmaxf(v, __shfl_xor_sync(0xffffffffu, v, 2));
    v = fmaxf(v, __shfl_xor_sync(0xffffffffu, v, 1));
    return v;
}
__device__ __forceinline__ float gelu_f(float x){
    float x3 = x*x*x;
    return 0.5f*x*(1.0f + tanhf(0.7978845608028654f*(x + 0.044715f*x3)));
}
static __device__ __forceinline__ uint32_t smem_u32(const void* p){
    uint32_t a;
    asm("{ .reg .u64 t; cvta.to.shared.u64 t, %1; cvt.u32.u64 %0, t; }" : "=r"(a) : "l"(p));
    return a;
}
static __device__ __forceinline__ void ldm4(uint32_t* r, uint32_t addr){
    asm volatile("ldmatrix.sync.aligned.m8n8.x4.shared.b16 {%0,%1,%2,%3}, [%4];"
        : "=r"(r[0]),"=r"(r[1]),"=r"(r[2]),"=r"(r[3]) : "r"(addr));
}
static __device__ __forceinline__ void mma_bf16(float* c, const uint32_t* a, const uint32_t* b){
    asm volatile("mma.sync.aligned.m16n8k16.row.col.f32.bf16.bf16.f32 "
        "{%0,%1,%2,%3}, {%4,%5,%6,%7}, {%8,%9}, {%0,%1,%2,%3};"
        : "+f"(c[0]),"+f"(c[1]),"+f"(c[2]),"+f"(c[3])
        : "r"(a[0]),"r"(a[1]),"r"(a[2]),"r"(a[3]), "r"(b[0]),"r"(b[1]));
}
static __device__ __forceinline__ void cpa16(uint32_t dst, const void* src){
    asm volatile("cp.async.ca.shared.global [%0], [%1], 16;" :: "r"(dst), "l"(src));
}
#define CPA_COMMIT() asm volatile("cp.async.commit_group;" ::: "memory")
#define CPA_WAIT2()  asm volatile("cp.async.wait_group 2;" ::: "memory")
static __device__ __forceinline__ uint32_t b2u(__nv_bfloat162 h){ return *(uint32_t*)&h; }
static __device__ __forceinline__ void split_bf(float v, __nv_bfloat16& hi, __nv_bfloat16& lo){
    hi = __float2bfloat16(v);
    lo = __float2bfloat16(v - __bfloat162float(hi));
}

// ---------- weight split prep ----------
__global__ void split_weights_kernel(const float* __restrict__ Wq, const float* __restrict__ Wk,
        const float* __restrict__ Wv, const float* __restrict__ Wo,
        const float* __restrict__ W1, const float* __restrict__ W2){
    int i4 = blockIdx.x*blockDim.x + threadIdx.x;
    if (i4 >= 3145728) return;
    int idx = i4*4;
    int l = idx / 3145728;
    int r = idx - l*3145728;
    const float* src;
    if (r < 786432){
        int n = r>>9, k = r&511;
        if (n < 512)       src = Wq + ((size_t)l*512 + n      )*512 + k;
        else if (n < 1024) src = Wk + ((size_t)l*512 + n - 512)*512 + k;
        else               src = Wv + ((size_t)l*512 + n -1024)*512 + k;
    } else if (r < 1048576){
        src = Wo + (size_t)l*262144 + (r - 786432);
    } else if (r < 2097152){
        src = W1 + (size_t)l*1048576 + (r - 1048576);
    } else {
        src = W2 + (size_t)l*1048576 + (r - 2097152);
    }
    float4 v = *(const float4*)src;
    __nv_bfloat162 h0 = __floats2bfloat162_rn(v.x, v.y);
    __nv_bfloat162 h1 = __floats2bfloat162_rn(v.z, v.w);
    float lx = v.x - __bfloat162float(h0.x);
    float ly = v.y - __bfloat162float(h0.y);
    float lz = v.z - __bfloat162float(h1.x);
    float lw = v.w - __bfloat162float(h1.y);
    __nv_bfloat162 e0 = __floats2bfloat162_rn(lx, ly);
    __nv_bfloat162 e1 = __floats2bfloat162_rn(lz, lw);
    *(uint2*)(g_whi + idx) = make_uint2(b2u(h0), b2u(h1));
    *(uint2*)(g_wlo + idx) = make_uint2(b2u(e0), b2u(e1));
}

// ---------- tensor-core GEMM: C[M,N] = A[M,K] @ W[N,K]^T (bf16 2-split, fp32 acc) ----------
// CTA tile 128x64, 8 warps (4m x 2n), K-chunk 32, 3-stage cp.async pipeline.
// stage buffer 30720B: Ahi[128x80B]@0, Alo@10240, Whi[64x80B]@20480, Wlo@25600.
#define GT_SMEM (3*30720)
// MODE 0: fp32 C (split-K partials if gridDim.z>1).  MODE 1: bias+gelu -> bf16 hi/lo out.
template<int MODE>
__global__ __launch_bounds__(256) void gemm_tc(
        const __nv_bfloat16* __restrict__ Ahi, const __nv_bfloat16* __restrict__ Alo,
        const __nv_bfloat16* __restrict__ Whi, const __nv_bfloat16* __restrict__ Wlo,
        const float* __restrict__ bias,
        float* __restrict__ C, __nv_bfloat16* __restrict__ Chi, __nv_bfloat16* __restrict__ Clo,
        int M, int N, int K){
    extern __shared__ char sm[];
    uint32_t sb = smem_u32(sm);
    int tid = threadIdx.x, wid = tid>>5, lane = tid&31;
    int n0 = blockIdx.x*64, m0 = blockIdx.y*128;
    int z = blockIdx.z, nz = gridDim.z;
    int ks = K/nz, kbeg = z*ks, CH = ks/32;
    int wm = (wid>>1)*32, wn = (wid&1)*32;

    float acc[2][4][4];
#pragma unroll
    for (int a = 0; a < 2; a++)
#pragma unroll
        for (int b = 0; b < 4; b++)
#pragma unroll
            for (int c = 0; c < 4; c++) acc[a][b][c] = 0.f;

    uint32_t a_addr = (uint32_t)((wm + (lane&15))*80 + ((lane>>4)<<4));
    uint32_t b_addr = (uint32_t)(20480 + (wn + (lane&7) + ((lane>>4)<<3))*80 + ((lane&8)<<1));

    auto issue_stage = [&](int c){
        if (c < CH){
            uint32_t st = sb + (c%3)*30720;
            int kk = kbeg + c*32;
#pragma unroll
            for (int u = 0; u < 6; u++){
                int i = u*256 + tid;
                uint32_t dst; const __nv_bfloat16* src;
                if (i < 512){
                    int row = i>>2, q = i&3;
                    dst = st + row*80 + q*16;
                    src = Ahi + (size_t)(m0+row)*K + kk + q*8;
                } else if (i < 1024){
                    int i2 = i-512, row = i2>>2, q = i2&3;
                    dst = st + 10240 + row*80 + q*16;
                    src = Alo + (size_t)(m0+row)*K + kk + q*8;
                } else if (i < 1280){
                    int i2 = i-1024, row = i2>>2, q = i2&3;
                    dst = st + 20480 + row*80 + q*16;
                    src = Whi + (size_t)(n0+row)*K + kk + q*8;
                } else {
                    int i2 = i-1280, row = i2>>2, q = i2&3;
                    dst = st + 25600 + row*80 + q*16;
                    src = Wlo + (size_t)(n0+row)*K + kk + q*8;
                }
                cpa16(dst, src);
            }
        }
        CPA_COMMIT();
    };

    issue_stage(0); issue_stage(1); issue_stage(2);

    for (int c = 0; c < CH; c++){
        CPA_WAIT2();
        __syncthreads();
        {
            uint32_t bufb = sb + (c%3)*30720;
#pragma unroll
            for (int s = 0; s < 2; s++){
                uint32_t ah[2][4], al[2][4], bh[2][4], bl[2][4];
                ldm4(ah[0], bufb + a_addr + s*32);
                ldm4(ah[1], bufb + a_addr + 16*80 + s*32);
                ldm4(al[0], bufb + a_addr + 10240 + s*32);
                ldm4(al[1], bufb + a_addr + 10240 + 16*80 + s*32);
                ldm4(bh[0], bufb + b_addr + s*32);
                ldm4(bh[1], bufb + b_addr + 16*80 + s*32);
                ldm4(bl[0], bufb + b_addr + 5120 + s*32);
                ldm4(bl[1], bufb + b_addr + 5120 + 16*80 + s*32);
#pragma unroll
                for (int mt = 0; mt < 2; mt++)
#pragma unroll
                    for (int nf = 0; nf < 4; nf++){
                        const uint32_t* Bh = &bh[nf>>1][(nf&1)*2];
                        const uint32_t* Bl = &bl[nf>>1][(nf&1)*2];
                        mma_bf16(acc[mt][nf], ah[mt], Bh);
                        mma_bf16(acc[mt][nf], ah[mt], Bl);
                        mma_bf16(acc[mt][nf], al[mt], Bh);
                    }
            }
        }
        __syncthreads();
        issue_stage(c+3);
    }
#pragma unroll
    for (int mt = 0; mt < 2; mt++){
        int r0 = m0 + wm + mt*16 + (lane>>2);
#pragma unroll
        for (int nf = 0; nf < 4; nf++){
            int col = n0 + wn + nf*8 + (lane&3)*2;
            float v0 = acc[mt][nf][0], v1 = acc[mt][nf][1];
            float v2 = acc[mt][nf][2], v3 = acc[mt][nf][3];
            if (MODE == 0){
                size_t zo = (nz > 1) ? (size_t)z*M*N : 0;
                *(float2*)(C + zo + (size_t)r0*N + col)     = make_float2(v0, v1);
                *(float2*)(C + zo + (size_t)(r0+8)*N + col) = make_float2(v2, v3);
            } else {
                float b0 = bias[col], b1 = bias[col+1];
                v0 = gelu_f(v0 + b0); v1 = gelu_f(v1 + b1);
                v2 = gelu_f(v2 + b0); v3 = gelu_f(v3 + b1);
                __nv_bfloat162 h0 = __floats2bfloat162_rn(v0, v1);
                __nv_bfloat162 h2 = __floats2bfloat162_rn(v2, v3);
                __nv_bfloat162 l0 = __floats2bfloat162_rn(v0 - __bfloat162float(h0.x),
                                                          v1 - __bfloat162float(h0.y));
                __nv_bfloat162 l2 = __floats2bfloat162_rn(v2 - __bfloat162float(h2.x),
                                                          v3 - __bfloat162float(h2.y));
                *(uint32_t*)(Chi + (size_t)r0*N + col)     = b2u(h0);
                *(uint32_t*)(Chi + (size_t)(r0+8)*N + col) = b2u(h2);
                *(uint32_t*)(Clo + (size_t)r0*N + col)     = b2u(l0);
                *(uint32_t*)(Clo + (size_t)(r0+8)*N + col) = b2u(l2);
            }
        }
    }
}

// ---------- prep kernels ----------
__global__ void init_buf_kernel(const float* __restrict__ hist){
    int idx = blockIdx.x*blockDim.x + threadIdx.x;
    if (idx >= 4*128*32) return;
    int i = idx & 31, t = (idx>>5)&127, b = idx>>12;
    g_buf[idx] = (t < 120) ? hist[(b*120 + t)*32 + i] : 0.0f;
}
__global__ void prep_pe_kernel(){
    int idx = blockIdx.x*blockDim.x + threadIdx.x;
    if (idx >= 128*512) return;
    int d = idx & 511, t = idx>>9;
    double freq = exp((double)(d & ~1) * (-9.210340371976184/512.0));
    double ang = (double)t * freq;
    g_pe[idx] = (float)((d & 1) ? cos(ang) : sin(ang));
}
__global__ __launch_bounds__(256) void prep_M_kernel(const float* __restrict__ Wr1,
        const float* __restrict__ W_emb, const float* __restrict__ b_emb,
        const float* __restrict__ br1){
    int j = blockIdx.x*8 + (threadIdx.x>>5);
    int lane = threadIdx.x&31;
    const float* wr = Wr1 + (size_t)j*1024;
    float a = 0.f;
    for (int k = 0; k < 512; k++) a = fmaf(wr[k], W_emb[k*32 + lane], a);
    g_M[lane*2048 + j] = a * EMB_SCALE;     // transposed [k][j]
    float c = 0.f;
    for (int k = lane; k < 512; k += 32) c = fmaf(wr[k], b_emb[k], c);
    c = warp_sum(c);
    if (lane == 0) g_c1[j] = c * EMB_SCALE + br1[j];
}

// ---------- embedding ----------
__global__ __launch_bounds__(512) void embed_kernel(const float* __restrict__ W_emb,
                                                    const float* __restrict__ b_emb){
    __shared__ float xs[32];
    int bt = blockIdx.x, t = bt & 127;
    if (threadIdx.x < 32) xs[threadIdx.x] = g_buf[bt*32 + threadIdx.x];
    __syncthreads();
    int d = threadIdx.x;
    const float* wr = W_emb + d*32;
    float acc = 0.f;
#pragma unroll
    for (int i = 0; i < 32; i++) acc = fmaf(wr[i], xs[i], acc);
    float y = (acc + b_emb[d]) * EMB_SCALE + g_pe[t*512 + d];
    g_h[bt*512 + d] = y;
    __nv_bfloat16 hi, lo; split_bf(y, hi, lo);
    g_hhi[bt*512 + d] = hi; g_hlo[bt*512 + d] = lo;
}

// ---------- attention (sums the 2 QKV split-K partials while loading) ----------
__global__ __launch_bounds__(256) void attn_kernel(){
    extern __shared__ float smf[];
    float* kt = smf;
    float* vs = kt + 64*129;
    float* qs = vs + 128*64;
    float* ws = qs + 32*64;
    const float* qp1 = g_qkv + 512*1536;
    int bh = blockIdx.x, b = bh>>3, h = bh&7;
    int q0 = blockIdx.y*32;
    int tid = threadIdx.x;
    for (int idx = tid; idx < 8192; idx += 256){
        int k = idx>>6, d = idx&63;
        int base = (b*128 + k)*1536 + h*64 + d;
        kt[d*129 + k] = g_qkv[base + 512] + qp1[base + 512];
        vs[k*64 + d]  = g_qkv[base + 1024] + qp1[base + 1024];
    }
    for (int idx = tid; idx < 2048; idx += 256){
        int r = idx>>6, d = idx&63;
        int base = (b*128 + q0 + r)*1536 + h*64 + d;
        qs[idx] = g_qkv[base] + qp1[base];
    }
    __syncthreads();
    int warp = tid>>5, lane = tid&31;
    int r0 = warp*4;
    float acc[4][4];
#pragma unroll
    for (int r = 0; r < 4; r++)
#pragma unroll
        for (int s = 0; s < 4; s++) acc[r][s] = 0.f;
#pragma unroll 4
    for (int d = 0; d < 64; d++){
        float k0v = kt[d*129 + lane];
        float k1v = kt[d*129 + 32 + lane];
        float k2v = kt[d*129 + 64 + lane];
        float k3v = kt[d*129 + 96 + lane];
#pragma unroll
        for (int r = 0; r < 4; r++){
            float qv = qs[(r0+r)*64 + d];
            acc[r][0] = fmaf(qv, k0v, acc[r][0]);
            acc[r][1] = fmaf(qv, k1v, acc[r][1]);
            acc[r][2] = fmaf(qv, k2v, acc[r][2]);
            acc[r][3] = fmaf(qv, k3v, acc[r][3]);
        }
    }
#pragma unroll
    for (int r = 0; r < 4; r++){
        int qi = q0 + r0 + r;
        float s[4];
#pragma unroll
        for (int sl = 0; sl < 4; sl++){
            int ki = sl*32 + lane;
            s[sl] = (ki > qi) ? acc[r][sl]*0.125f : NEGMIN;
        }
        float mx = fmaxf(fmaxf(s[0], s[1]), fmaxf(s[2], s[3]));
        mx = warp_max(mx);
        float e[4], sum = 0.f;
#pragma unroll
        for (int sl = 0; sl < 4; sl++){ e[sl] = expf(s[sl] - mx); sum += e[sl]; }
        sum = warp_sum(sum);
        float inv = 1.0f/sum;
#pragma unroll
        for (int sl = 0; sl < 4; sl++)
            ws[(warp*4 + r)*128 + sl*32 + lane] = e[sl]*inv;
    }
    __syncwarp();
    float o0[4] = {0,0,0,0}, o1[4] = {0,0,0,0};
#pragma unroll 4
    for (int k = 0; k < 128; k++){
        float v0 = vs[k*64 + lane];
        float v1 = vs[k*64 + 32 + lane];
#pragma unroll
        for (int r = 0; r < 4; r++){
            float wv = ws[(warp*4 + r)*128 + k];
            o0[r] = fmaf(wv, v0, o0[r]);
            o1[r] = fmaf(wv, v1, o1[r]);
        }
    }
#pragma unroll
    for (int r = 0; r < 4; r++){
        int row = (b*128 + q0 + r0 + r)*512 + h*64;
        __nv_bfloat16 hi, lo;
        split_bf(o0[r], hi, lo);
        g_athi[row + lane] = hi; g_atlo[row + lane] = lo;
        split_bf(o1[r], hi, lo);
        g_athi[row + 32 + lane] = hi; g_atlo[row + 32 + lane] = lo;
    }
}

// ---------- LayerNorm: residual + 4 split-K partials + optional bias; emits fp32 + bf16 hi/lo ----------
__global__ __launch_bounds__(256) void ln_kernel(float* __restrict__ h,
        const float* __restrict__ parts, const float* __restrict__ bias,
        const float* __restrict__ gw, const float* __restrict__ bw){
    const int MN = 512*512;
    __shared__ float red[8];
    __shared__ float bc;
    int tid = threadIdx.x;
    int base = blockIdx.x*512;
    float x0 = h[base+tid]     + parts[base+tid]     + parts[MN+base+tid]
             + parts[2*MN+base+tid]     + parts[3*MN+base+tid];
    float x1 = h[base+tid+256] + parts[base+tid+256] + parts[MN+base+tid+256]
             + parts[2*MN+base+tid+256] + parts[3*MN+base+tid+256];
    if (bias){ x0 += bias[tid]; x1 += bias[tid+256]; }
    float s = warp_sum(x0 + x1);
    if ((tid&31) == 0) red[tid>>5] = s;
    __syncthreads();
    if (tid == 0){ float t = 0.f; for (int i = 0; i < 8; i++) t += red[i]; bc = t*(1.f/512.f); }
    __syncthreads();
    float mu = bc;
    float d0 = x0 - mu, d1 = x1 - mu;
    float v = warp_sum(d0*d0 + d1*d1);
    if ((tid&31) == 0) red[tid>>5] = v;
    __syncthreads();
    if (tid == 0){ float t = 0.f; for (int i = 0; i < 8; i++) t += red[i]; bc = rsqrtf(t*(1.f/512.f) + LN_EPS); }
    __syncthreads();
    float r = bc;
    float y0 = d0*r*gw[tid]     + bw[tid];
    float y1 = d1*r*gw[tid+256] + bw[tid+256];
    h[base+tid]     = y0;
    h[base+tid+256] = y1;
    __nv_bfloat16 hi, lo;
    split_bf(y0, hi, lo); g_hhi[base+tid] = hi;     g_hlo[base+tid] = lo;
    split_bf(y1, hi, lo); g_hhi[base+tid+256] = hi; g_hlo[base+tid+256] = lo;
}

// ---------- refine part 1 ----------
__global__ __launch_bounds__(256) void refine_basev(const float* __restrict__ Wr1, int step){
    __shared__ float ctx[512];
    int g = blockIdx.x, b = blockIdx.y;
    int tid = threadIdx.x, warp = tid>>5, lane = tid&31;
    int row = b*128 + 119 + step;
    for (int i = tid; i < 512; i += 256) ctx[i] = g_h[row*512 + i];
    __syncthreads();
#pragma unroll
    for (int r = 0; r < 16; r++){
        int j = g*128 + warp*16 + r;
        const float* wr = Wr1 + (size_t)j*1024 + 512;
        float a = 0.f;
#pragma unroll
        for (int k = lane; k < 512; k += 32) a = fmaf(wr[k], ctx[k], a);
        a = warp_sum(a);
        if (lane == 0) g_basev[b*2048 + j] = a + g_c1[j];
    }
}

// ---------- refine part 2 ----------
__global__ __launch_bounds__(512) void refine_iter(const float* __restrict__ Wr2,
        const float* __restrict__ br2, float* __restrict__ out, int step){
    __shared__ float cur[32];
    __shared__ float basev_s[2048];
    __shared__ float hid[2048];
    __shared__ float outp[32];
    int b = blockIdx.x, tid = threadIdx.x, warp = tid>>5, lane = tid&31;
    int row = b*128 + 119 + step;
    for (int i = tid; i < 2048; i += 512) basev_s[i] = g_basev[b*2048 + i];
    if (tid < 32) cur[tid] = g_buf[row*32 + tid];
    __syncthreads();
    for (int it = 0; it < 5; it++){
#pragma unroll
        for (int c = 0; c < 4; c++){
            int j = c*512 + tid;
            float p = basev_s[j];
#pragma unroll
            for (int k = 0; k < 32; k++) p = fmaf(g_M[k*2048 + j], cur[k], p);
            hid[j] = gelu_f(p);
        }
        __syncthreads();
#pragma unroll
        for (int ii = 0; ii < 2; ii++){
            int i = warp*2 + ii;
            const float* w2 = Wr2 + (size_t)i*2048;
            float p = 0.f;
#pragma unroll 8
            for (int k = lane; k < 2048; k += 32) p = fmaf(w2[k], hid[k], p);
            p = warp_sum(p);
            if (lane == 0) outp[i] = p;
        }
        __syncthreads();
        if (tid < 32) cur[tid] += outp[tid] + br2[tid];
        __syncthreads();
    }
    if (tid < 32){
        float v = cur[tid];
        g_buf[(row+1)*32 + tid] = v;
        out[(b*8 + step)*32 + tid] = v;
    }
}

// ---------- host ----------
#define ATTN_SMEM (22592*4)

extern "C" void kernel_launch(void* const* d_in, const int* in_sizes, int n_in,
                              void* d_out, int out_size){
    const float* hist  = (const float*)d_in[0];
    const float* W_emb = (const float*)d_in[2];
    const float* b_emb = (const float*)d_in[3];
    const float* Wq    = (const float*)d_in[4];
    const float* Wk    = (const float*)d_in[5];
    const float* Wv    = (const float*)d_in[6];
    const float* Wo    = (const float*)d_in[7];
    const float* ln1g  = (const float*)d_in[8];
    const float* ln1b  = (const float*)d_in[9];
    const float* W1    = (const float*)d_in[10];
    const float* b1    = (const float*)d_in[11];
    const float* W2    = (const float*)d_in[12];
    const float* b2    = (const float*)d_in[13];
    const float* ln2g  = (const float*)d_in[14];
    const float* ln2b  = (const float*)d_in[15];
    const float* Wr1   = (const float*)d_in[16];
    const float* br1   = (const float*)d_in[17];
    const float* Wr2   = (const float*)d_in[18];
    const float* br2   = (const float*)d_in[19];
    float* out = (float*)d_out;

    cudaFuncSetAttribute(attn_kernel, cudaFuncAttributeMaxDynamicSharedMemorySize, ATTN_SMEM);
    cudaFuncSetAttribute(gemm_tc<0>, cudaFuncAttributeMaxDynamicSharedMemorySize, GT_SMEM);
    cudaFuncSetAttribute(gemm_tc<1>, cudaFuncAttributeMaxDynamicSharedMemorySize, GT_SMEM);

    float *ph, *pqkv2, *pt2;
    __nv_bfloat16 *pwhi, *pwlo, *phhi, *phlo, *pathi, *patlo, *pffhi, *pfflo;
    cudaGetSymbolAddress((void**)&ph,    g_h);
    cudaGetSymbolAddress((void**)&pqkv2, g_qkv);
    cudaGetSymbolAddress((void**)&pt2,   g_t2);
    cudaGetSymbolAddress((void**)&pwhi,  g_whi);
    cudaGetSymbolAddress((void**)&pwlo,  g_wlo);
    cudaGetSymbolAddress((void**)&phhi,  g_hhi);
    cudaGetSymbolAddress((void**)&phlo,  g_hlo);
    cudaGetSymbolAddress((void**)&pathi, g_athi);
    cudaGetSymbolAddress((void**)&patlo, g_atlo);
    cudaGetSymbolAddress((void**)&pffhi, g_ffhi);
    cudaGetSymbolAddress((void**)&pfflo, g_fflo);

    init_buf_kernel<<<(4*128*32 + 255)/256, 256>>>(hist);
    split_weights_kernel<<<(3145728 + 255)/256, 256>>>(Wq, Wk, Wv, Wo, W1, W2);
    prep_pe_kernel<<<(128*512 + 255)/256, 256>>>();
    prep_M_kernel<<<256, 256>>>(Wr1, W_emb, b_emb, br1);

    for (int step = 0; step < 8; step++){
        embed_kernel<<<512, 512>>>(W_emb, b_emb);
        for (int l = 0; l < 4; l++){
            size_t LB = (size_t)l*3145728;
            gemm_tc<0><<<dim3(24,4,2), 256, GT_SMEM>>>(phhi, phlo, pwhi+LB, pwlo+LB,
                    nullptr, pqkv2, nullptr, nullptr, 512, 1536, 512);
            attn_kernel<<<dim3(32,4), 256, ATTN_SMEM>>>();
            gemm_tc<0><<<dim3(8,4,4), 256, GT_SMEM>>>(pathi, patlo, pwhi+LB+786432, pwlo+LB+786432,
                    nullptr, pt2, nullptr, nullptr, 512, 512, 512);
            ln_kernel<<<512, 256>>>(ph, pt2, nullptr, ln1g + l*512, ln1b + l*512);
            gemm_tc<1><<<dim3(32,4,1), 256, GT_SMEM>>>(phhi, phlo, pwhi+LB+1048576, pwlo+LB+1048576,
                    b1 + l*2048, nullptr, pffhi, pfflo, 512, 2048, 512);
            gemm_tc<0><<<dim3(8,4,4), 256, GT_SMEM>>>(pffhi, pfflo, pwhi+LB+2097152, pwlo+LB+2097152,
                    nullptr, pt2, nullptr, nullptr, 512, 512, 2048);
            ln_kernel<<<512, 256>>>(ph, pt2, b2 + l*512, ln2g + l*512, ln2b + l*512);
        }
        refine_basev<<<dim3(16,4), 256>>>(Wr1, step);
        refine_iter<<<4, 512>>>(Wr2, br2, out, step);
    }
}